// round 2
// baseline (speedup 1.0000x reference)
#include <cuda_runtime.h>
#include <cuda_bf16.h>
#include <math.h>

// Shapes are fixed by the problem: B=16384, D=64, H=1024, CLAMP=10.
#define B_ROWS 16384
#define D_DIM  64
#define H_DIM  1024
#define CLAMPV 10.0f

// Packed weights, per step i (3072 floats each):
//   [0,1024)    : W1m column i   (masked, m0-sorted, lane-major packed)
//   [1024,2048) : W2m row i      (mu row, masked)
//   [2048,3072) : W2m row 64+i   (alpha row, masked)
// Lane-major packing: packed[l*32 + k] holds sorted-position p = l + 32*k.
__device__ __align__(16) float g_w[64 * 3072];
__device__ __align__(16) float g_b1p[H_DIM];

// m0[h] = h % 63, values 0..62. Sorted by m0 (stable).
// start_ge(v) = number of units with m0 < v.
__host__ __device__ __forceinline__ int start_ge(int v) {
    return (v <= 16) ? 17 * v : 16 * v + 16;
}

__device__ __forceinline__ float tanh_fast(float x) {
    // tanh(x) = 1 - 2/(exp(2x)+1). MUFU EX2 + RCP; ~1e-7 abs error near 0
    // (MUFU.TANH's 5e-4 absolute error would be too coarse for log_det).
    float e = __expf(2.0f * x);
    return 1.0f - __fdividef(2.0f, e + 1.0f);
}

// ---------------- prep: permute + mask + pack weights ----------------
__global__ void maf_prep(const float* __restrict__ W1,
                         const float* __restrict__ b1,
                         const float* __restrict__ W2) {
    int gid = blockIdx.x * blockDim.x + threadIdx.x;
    if (gid >= 64 * 3072) return;
    int i   = gid / 3072;
    int rem = gid - i * 3072;
    int sec = rem >> 10;        // 0: W1 col, 1: mu row, 2: alpha row
    int j   = rem & 1023;       // packed index
    int l = j >> 5, k = j & 31;
    int p = l + 32 * k;         // sorted position this slot represents
    // inverse permutation: sorted position -> (v = m0 value, k2 = index in group)
    int v, k2;
    if (p < 272) { v = p / 17; k2 = p - v * 17; }
    else         { int r = p - 272; v = 16 + (r >> 4); k2 = r & 15; }
    int h = v + 63 * k2;        // original unit index

    float val;
    if (sec == 0)      val = (i <= v)            ? W1[h * 64 + i]          : 0.0f;
    else if (sec == 1) val = (v < (i >> 1))      ? W2[i * 1024 + h]        : 0.0f;
    else               val = (v < 32 + (i >> 1)) ? W2[(64 + i) * 1024 + h] : 0.0f;
    g_w[gid] = val;

    if (gid < 1024) {
        int jl = gid >> 5, jk = gid & 31;
        int pp = jl + 32 * jk;
        int vv, kk2;
        if (pp < 272) { vv = pp / 17; kk2 = pp - vv * 17; }
        else          { int r = pp - 272; vv = 16 + (r >> 4); kk2 = r & 15; }
        g_b1p[gid] = b1[vv + 63 * kk2];
    }
}

// ---------------- main: 1 warp = 2 rows, 32 units/lane ----------------
__global__ void __launch_bounds__(256) maf_main(
    const float* __restrict__ z, const float* __restrict__ b2,
    float* __restrict__ out_x, float* __restrict__ out_ld)
{
    const int l    = threadIdx.x & 31;
    const int warp = blockIdx.x * (blockDim.x >> 5) + (threadIdx.x >> 5);
    const int r0 = warp * 2, r1 = r0 + 1;

    float s0[32], s1[32], t0[32], t1[32];

    // init s = b1 (x starts at zero), t = tanh(s)
    const float4* b1v = (const float4*)(g_b1p) + l * 8;
#pragma unroll
    for (int kb = 0; kb < 8; kb++) {
        float4 b = b1v[kb];
        s0[4*kb+0] = b.x; s0[4*kb+1] = b.y; s0[4*kb+2] = b.z; s0[4*kb+3] = b.w;
        s1[4*kb+0] = b.x; s1[4*kb+1] = b.y; s1[4*kb+2] = b.z; s1[4*kb+3] = b.w;
    }
#pragma unroll
    for (int k = 0; k < 32; k++) {
        float tv = tanh_fast(s0[k]);
        t0[k] = tv; t1[k] = tv;
    }

    // preload z: lane l holds columns 2l, 2l+1 of each row
    float zA0 = z[r0 * 64 + 2 * l], zA1 = z[r0 * 64 + 2 * l + 1];
    float zB0 = z[r1 * 64 + 2 * l], zB1 = z[r1 * 64 + 2 * l + 1];

    float xlo0 = 0.f, xhi0 = 0.f, xlo1 = 0.f, xhi1 = 0.f;
    float ld0 = 0.f, ld1 = 0.f;

#pragma unroll 1
    for (int i = 0; i < 64; i++) {
        const float* wb = g_w + i * 3072;
        const float4* wmu = (const float4*)(wb + 1024) + l * 8;
        const float4* wal = (const float4*)(wb + 2048) + l * 8;

        // dots: masked weights are pre-zeroed, so run full width.
        float m0a = 0.f, m0b = 0.f, m1a = 0.f, m1b = 0.f;
        float a0a = 0.f, a0b = 0.f, a1a = 0.f, a1b = 0.f;
#pragma unroll
        for (int kb = 0; kb < 8; kb++) {
            float4 wm = wmu[kb];
            float4 wa = wal[kb];
            m0a = fmaf(t0[4*kb+0], wm.x, m0a); m0b = fmaf(t0[4*kb+1], wm.y, m0b);
            m0a = fmaf(t0[4*kb+2], wm.z, m0a); m0b = fmaf(t0[4*kb+3], wm.w, m0b);
            m1a = fmaf(t1[4*kb+0], wm.x, m1a); m1b = fmaf(t1[4*kb+1], wm.y, m1b);
            m1a = fmaf(t1[4*kb+2], wm.z, m1a); m1b = fmaf(t1[4*kb+3], wm.w, m1b);
            a0a = fmaf(t0[4*kb+0], wa.x, a0a); a0b = fmaf(t0[4*kb+1], wa.y, a0b);
            a0a = fmaf(t0[4*kb+2], wa.z, a0a); a0b = fmaf(t0[4*kb+3], wa.w, a0b);
            a1a = fmaf(t1[4*kb+0], wa.x, a1a); a1b = fmaf(t1[4*kb+1], wa.y, a1b);
            a1a = fmaf(t1[4*kb+2], wa.z, a1a); a1b = fmaf(t1[4*kb+3], wa.w, a1b);
        }
        float pm0 = m0a + m0b, pa0 = a0a + a0b;
        float pm1 = m1a + m1b, pa1 = a1a + a1b;
#pragma unroll
        for (int off = 16; off; off >>= 1) {
            pm0 += __shfl_xor_sync(0xffffffffu, pm0, off);
            pa0 += __shfl_xor_sync(0xffffffffu, pa0, off);
            pm1 += __shfl_xor_sync(0xffffffffu, pm1, off);
            pa1 += __shfl_xor_sync(0xffffffffu, pa1, off);
        }

        float b2mu = __ldg(b2 + i);
        float b2al = __ldg(b2 + 64 + i);
        float mu0 = fminf(fmaxf(pm0 + b2mu, -CLAMPV), CLAMPV);
        float mu1 = fminf(fmaxf(pm1 + b2mu, -CLAMPV), CLAMPV);
        float aa0 = fminf(fmaxf(pa0 + b2al, -CLAMPV), CLAMPV);
        float aa1 = fminf(fmaxf(pa1 + b2al, -CLAMPV), CLAMPV);

        float zi0 = __shfl_sync(0xffffffffu, (i & 1) ? zA1 : zA0, i >> 1);
        float zi1 = __shfl_sync(0xffffffffu, (i & 1) ? zB1 : zB0, i >> 1);
        float x0 = fmaf(zi0, __expf(aa0), mu0);
        float x1 = fmaf(zi1, __expf(aa1), mu1);
        ld0 += aa0; ld1 += aa1;
        if ((i >> 1) == l) {
            if (i & 1) { xhi0 = x0; xhi1 = x1; }
            else       { xlo0 = x0; xlo1 = x1; }
        }

        // rank-1 update: s += W1m[:,i] * x_i  (zero weights mask the suffix)
        const float4* w1 = (const float4*)(wb) + l * 8;
#pragma unroll
        for (int kb = 0; kb < 8; kb++) {
            float4 w = w1[kb];
            s0[4*kb+0] = fmaf(w.x, x0, s0[4*kb+0]);
            s0[4*kb+1] = fmaf(w.y, x0, s0[4*kb+1]);
            s0[4*kb+2] = fmaf(w.z, x0, s0[4*kb+2]);
            s0[4*kb+3] = fmaf(w.w, x0, s0[4*kb+3]);
            s1[4*kb+0] = fmaf(w.x, x1, s1[4*kb+0]);
            s1[4*kb+1] = fmaf(w.y, x1, s1[4*kb+1]);
            s1[4*kb+2] = fmaf(w.z, x1, s1[4*kb+2]);
            s1[4*kb+3] = fmaf(w.w, x1, s1[4*kb+3]);
        }

        // lazy tanh refresh: only [start_ge(i), start_ge(32 + (i+1)/2))
        int S  = start_ge(i);
        int v2 = 32 + ((i + 1) >> 1);
        int E2 = start_ge(v2); if (E2 > 1024) E2 = 1024;
        int kLo = (S - l + 31) >> 5;            // ceil((S-l)/32), >= 0
        int kHi = (E2 - l + 31) >> 5;           // ceil((E2-l)/32)
#pragma unroll
        for (int k = 0; k < 32; k++) {
            if (k >= kLo && k < kHi) {
                t0[k] = tanh_fast(s0[k]);
                t1[k] = tanh_fast(s1[k]);
            }
        }
    }

    // epilogue: NaN/Inf cleanup + stores
    if (!isfinite(xlo0)) xlo0 = 0.f;
    if (!isfinite(xhi0)) xhi0 = 0.f;
    if (!isfinite(xlo1)) xlo1 = 0.f;
    if (!isfinite(xhi1)) xhi1 = 0.f;
    out_x[r0 * 64 + 2 * l]     = xlo0;
    out_x[r0 * 64 + 2 * l + 1] = xhi0;
    out_x[r1 * 64 + 2 * l]     = xlo1;
    out_x[r1 * 64 + 2 * l + 1] = xhi1;
    if (l == 0) {
        if (!isfinite(ld0)) ld0 = 0.f;
        if (!isfinite(ld1)) ld1 = 0.f;
        out_ld[r0] = ld0;
        out_ld[r1] = ld1;
    }
}

extern "C" void kernel_launch(void* const* d_in, const int* in_sizes, int n_in,
                              void* d_out, int out_size) {
    const float* z  = (const float*)d_in[0];   // (16384, 64)
    const float* W1 = (const float*)d_in[1];   // (1024, 64)
    const float* b1 = (const float*)d_in[2];   // (1024,)
    const float* W2 = (const float*)d_in[3];   // (128, 1024)
    const float* b2 = (const float*)d_in[4];   // (128,)
    float* out    = (float*)d_out;
    float* out_x  = out;                       // x: 16384*64 floats
    float* out_ld = out + B_ROWS * D_DIM;      // log_det: 16384 floats

    maf_prep<<<768, 256>>>(W1, b1, W2);        // 64*3072 elements
    maf_main<<<1024, 256>>>(z, b2, out_x, out_ld);  // 8192 warps, 2 rows each
}

// round 3
// speedup vs baseline: 1.9463x; 1.9463x over previous
#include <cuda_runtime.h>
#include <cuda_bf16.h>
#include <math.h>

// Shapes fixed by the problem: B=16384, D=64, H=1024, CLAMP=10.
#define B_ROWS 16384
#define D_DIM  64
#define H_DIM  1024
#define CLAMPV 10.0f

// Packed weights, per step i (3072 floats each):
//   [0,1024)    : W1m column i   (masked, m0-sorted)
//   [1024,2048) : W2m row i      (mu row, masked)
//   [2048,3072) : W2m row 64+i   (alpha row, masked)
// COALESCED packing: packed index j == sorted position p (identity).
// Lane l, float4-chunk kb reads floats [kb*128 + l*4, +4)  ->  warp-contiguous
// 512B per chunk = 4 L1 wavefronts per LDG.128 (was 32 with lane-major).
__device__ __align__(16) float g_w[64 * 3072];
__device__ __align__(16) float g_b1p[H_DIM];

// m0[h] = h % 63 (values 0..62), H sorted stably by m0.
// start_ge(v) = # units with m0 < v.  v in [0,16): 17 members; [16,63): 16.
__host__ __device__ __forceinline__ int start_ge(int v) {
    return (v <= 16) ? 17 * v : 16 * v + 16;
}

__device__ __forceinline__ float tanh_fast(float x) {
    // tanh(x) = 1 - 2/(exp(2x)+1): MUFU EX2 + RCP, ~1e-7 abs error
    // (MUFU.TANH's ~5e-4 abs error is too coarse: alphas are ~1e-3).
    float e = __expf(2.0f * x);
    return 1.0f - __fdividef(2.0f, e + 1.0f);
}

// ---------------- prep: permute + mask + pack weights ----------------
__global__ void maf_prep(const float* __restrict__ W1,
                         const float* __restrict__ b1,
                         const float* __restrict__ W2) {
    int gid = blockIdx.x * blockDim.x + threadIdx.x;
    if (gid >= 64 * 3072) return;
    int i   = gid / 3072;
    int rem = gid - i * 3072;
    int sec = rem >> 10;        // 0: W1 col, 1: mu row, 2: alpha row
    int p   = rem & 1023;       // packed index == sorted position (identity)
    // inverse permutation: sorted position -> (v = m0 value, k2 = index in group)
    int v, k2;
    if (p < 272) { v = p / 17; k2 = p - v * 17; }
    else         { int r = p - 272; v = 16 + (r >> 4); k2 = r & 15; }
    int h = v + 63 * k2;        // original unit index

    float val;
    if (sec == 0)      val = (i <= v)            ? W1[h * 64 + i]          : 0.0f;
    else if (sec == 1) val = (v < (i >> 1))      ? W2[i * 1024 + h]        : 0.0f;
    else               val = (v < 32 + (i >> 1)) ? W2[(64 + i) * 1024 + h] : 0.0f;
    g_w[gid] = val;

    if (gid < 1024) {
        int pp = gid;
        int vv, kk;
        if (pp < 272) { vv = pp / 17; kk = pp - vv * 17; }
        else          { int r = pp - 272; vv = 16 + (r >> 4); kk = r & 15; }
        g_b1p[gid] = b1[vv + 63 * kk];
    }
}

// ---------------- main: 1 warp = 2 rows, 32 units/lane ----------------
// Lane l's register k (= kb*4+e) holds sorted position p = kb*128 + l*4 + e.
__global__ void __launch_bounds__(320) maf_main(
    const float* __restrict__ z, const float* __restrict__ b2,
    float* __restrict__ out_x, float* __restrict__ out_ld)
{
    const int l    = threadIdx.x & 31;
    const int warp = blockIdx.x * (blockDim.x >> 5) + (threadIdx.x >> 5);
    if (warp >= B_ROWS / 2) return;
    const int r0 = warp * 2, r1 = r0 + 1;

    float s0[32], s1[32], t0[32], t1[32];

    // init s = b1 (x starts at zero), t = tanh(s)
    const float4* b1v = (const float4*)(g_b1p);
#pragma unroll
    for (int kb = 0; kb < 8; kb++) {
        float4 b = b1v[kb * 32 + l];
        s0[4*kb+0] = b.x; s0[4*kb+1] = b.y; s0[4*kb+2] = b.z; s0[4*kb+3] = b.w;
        s1[4*kb+0] = b.x; s1[4*kb+1] = b.y; s1[4*kb+2] = b.z; s1[4*kb+3] = b.w;
    }
#pragma unroll
    for (int k = 0; k < 32; k++) {
        float tv = tanh_fast(s0[k]);
        t0[k] = tv; t1[k] = tv;
    }

    // preload z: lane l holds columns 2l, 2l+1 of each row
    float zA0 = z[r0 * 64 + 2 * l], zA1 = z[r0 * 64 + 2 * l + 1];
    float zB0 = z[r1 * 64 + 2 * l], zB1 = z[r1 * 64 + 2 * l + 1];
    // preload b2: lane l holds b2[2l], b2[2l+1], b2[64+2l], b2[64+2l+1]
    float bmu_lo = b2[2 * l], bmu_hi = b2[2 * l + 1];
    float bal_lo = b2[64 + 2 * l], bal_hi = b2[64 + 2 * l + 1];

    float xlo0 = 0.f, xhi0 = 0.f, xlo1 = 0.f, xhi1 = 0.f;
    float ld0 = 0.f, ld1 = 0.f;

#pragma unroll 1
    for (int i = 0; i < 64; i++) {
        const float* wb = g_w + i * 3072;
        const float4* wmu = (const float4*)(wb + 1024);
        const float4* wal = (const float4*)(wb + 2048);

        // dots: masked weights are pre-zeroed, so run full width.
        float m0a = 0.f, m0b = 0.f, m1a = 0.f, m1b = 0.f;
        float a0a = 0.f, a0b = 0.f, a1a = 0.f, a1b = 0.f;
#pragma unroll
        for (int kb = 0; kb < 8; kb++) {
            float4 wm = wmu[kb * 32 + l];
            float4 wa = wal[kb * 32 + l];
            m0a = fmaf(t0[4*kb+0], wm.x, m0a); m0b = fmaf(t0[4*kb+1], wm.y, m0b);
            m0a = fmaf(t0[4*kb+2], wm.z, m0a); m0b = fmaf(t0[4*kb+3], wm.w, m0b);
            m1a = fmaf(t1[4*kb+0], wm.x, m1a); m1b = fmaf(t1[4*kb+1], wm.y, m1b);
            m1a = fmaf(t1[4*kb+2], wm.z, m1a); m1b = fmaf(t1[4*kb+3], wm.w, m1b);
            a0a = fmaf(t0[4*kb+0], wa.x, a0a); a0b = fmaf(t0[4*kb+1], wa.y, a0b);
            a0a = fmaf(t0[4*kb+2], wa.z, a0a); a0b = fmaf(t0[4*kb+3], wa.w, a0b);
            a1a = fmaf(t1[4*kb+0], wa.x, a1a); a1b = fmaf(t1[4*kb+1], wa.y, a1b);
            a1a = fmaf(t1[4*kb+2], wa.z, a1b == a1b ? a1a : a1a); // keep ordering simple
            a1a = fmaf(0.f, 0.f, a1a); // no-op guard removed below
            a1a = a1a; // (see clean accumulation below)
            a1b = fmaf(t1[4*kb+3], wa.w, a1b);
        }
        // NOTE: the two dummy lines above must not change math; rewrite cleanly:
        // (they were folded out; real accumulation for a1a done here)
        // -- a1a already accumulated wa.x/wa.z? ensure correctness by redoing:
        // To avoid any ambiguity, recompute a1a/a1b from scratch:
        a1a = 0.f; a1b = 0.f;
#pragma unroll
        for (int kb = 0; kb < 8; kb++) {
            float4 wa = wal[kb * 32 + l];
            a1a = fmaf(t1[4*kb+0], wa.x, a1a); a1b = fmaf(t1[4*kb+1], wa.y, a1b);
            a1a = fmaf(t1[4*kb+2], wa.z, a1a); a1b = fmaf(t1[4*kb+3], wa.w, a1b);
        }

        float pm0 = m0a + m0b, pa0 = a0a + a0b;
        float pm1 = m1a + m1b, pa1 = a1a + a1b;
#pragma unroll
        for (int off = 16; off; off >>= 1) {
            pm0 += __shfl_xor_sync(0xffffffffu, pm0, off);
            pa0 += __shfl_xor_sync(0xffffffffu, pa0, off);
            pm1 += __shfl_xor_sync(0xffffffffu, pm1, off);
            pa1 += __shfl_xor_sync(0xffffffffu, pa1, off);
        }

        float b2mu = __shfl_sync(0xffffffffu, (i & 1) ? bmu_hi : bmu_lo, i >> 1);
        float b2al = __shfl_sync(0xffffffffu, (i & 1) ? bal_hi : bal_lo, i >> 1);
        float mu0 = fminf(fmaxf(pm0 + b2mu, -CLAMPV), CLAMPV);
        float mu1 = fminf(fmaxf(pm1 + b2mu, -CLAMPV), CLAMPV);
        float aa0 = fminf(fmaxf(pa0 + b2al, -CLAMPV), CLAMPV);
        float aa1 = fminf(fmaxf(pa1 + b2al, -CLAMPV), CLAMPV);

        float zi0 = __shfl_sync(0xffffffffu, (i & 1) ? zA1 : zA0, i >> 1);
        float zi1 = __shfl_sync(0xffffffffu, (i & 1) ? zB1 : zB0, i >> 1);
        float x0 = fmaf(zi0, __expf(aa0), mu0);
        float x1 = fmaf(zi1, __expf(aa1), mu1);
        ld0 += aa0; ld1 += aa1;
        if ((i >> 1) == l) {
            if (i & 1) { xhi0 = x0; xhi1 = x1; }
            else       { xlo0 = x0; xlo1 = x1; }
        }

        // rank-1 update: s += W1m[:,i] * x_i  (zero weights mask the suffix)
        const float4* w1 = (const float4*)(wb);
#pragma unroll
        for (int kb = 0; kb < 8; kb++) {
            float4 w = w1[kb * 32 + l];
            s0[4*kb+0] = fmaf(w.x, x0, s0[4*kb+0]);
            s0[4*kb+1] = fmaf(w.y, x0, s0[4*kb+1]);
            s0[4*kb+2] = fmaf(w.z, x0, s0[4*kb+2]);
            s0[4*kb+3] = fmaf(w.w, x0, s0[4*kb+3]);
            s1[4*kb+0] = fmaf(w.x, x1, s1[4*kb+0]);
            s1[4*kb+1] = fmaf(w.y, x1, s1[4*kb+1]);
            s1[4*kb+2] = fmaf(w.z, x1, s1[4*kb+2]);
            s1[4*kb+3] = fmaf(w.w, x1, s1[4*kb+3]);
        }

        // lazy tanh refresh on [start_ge(i), start_ge(32 + (i+1)/2)),
        // chunk-granular (register block kb covers p in [kb*128+4l, +4);
        // over-refresh is always safe).
        int S  = start_ge(i);
        int v2 = 32 + ((i + 1) >> 1);
        int E2 = start_ge(v2); if (E2 > 1024) E2 = 1024;
#pragma unroll
        for (int kb = 0; kb < 8; kb++) {
            int pb = kb * 128 + l * 4;
            if (pb < E2 && pb + 4 > S) {
                t0[4*kb+0] = tanh_fast(s0[4*kb+0]);
                t0[4*kb+1] = tanh_fast(s0[4*kb+1]);
                t0[4*kb+2] = tanh_fast(s0[4*kb+2]);
                t0[4*kb+3] = tanh_fast(s0[4*kb+3]);
                t1[4*kb+0] = tanh_fast(s1[4*kb+0]);
                t1[4*kb+1] = tanh_fast(s1[4*kb+1]);
                t1[4*kb+2] = tanh_fast(s1[4*kb+2]);
                t1[4*kb+3] = tanh_fast(s1[4*kb+3]);
            }
        }
    }

    // epilogue: NaN/Inf cleanup + stores
    if (!isfinite(xlo0)) xlo0 = 0.f;
    if (!isfinite(xhi0)) xhi0 = 0.f;
    if (!isfinite(xlo1)) xlo1 = 0.f;
    if (!isfinite(xhi1)) xhi1 = 0.f;
    out_x[r0 * 64 + 2 * l]     = xlo0;
    out_x[r0 * 64 + 2 * l + 1] = xhi0;
    out_x[r1 * 64 + 2 * l]     = xlo1;
    out_x[r1 * 64 + 2 * l + 1] = xhi1;
    if (l == 0) {
        if (!isfinite(ld0)) ld0 = 0.f;
        if (!isfinite(ld1)) ld1 = 0.f;
        out_ld[r0] = ld0;
        out_ld[r1] = ld1;
    }
}

extern "C" void kernel_launch(void* const* d_in, const int* in_sizes, int n_in,
                              void* d_out, int out_size) {
    const float* z  = (const float*)d_in[0];   // (16384, 64)
    const float* W1 = (const float*)d_in[1];   // (1024, 64)
    const float* b1 = (const float*)d_in[2];   // (1024,)
    const float* W2 = (const float*)d_in[3];   // (128, 1024)
    const float* b2 = (const float*)d_in[4];   // (128,)
    float* out    = (float*)d_out;
    float* out_x  = out;                       // x: 16384*64 floats
    float* out_ld = out + B_ROWS * D_DIM;      // log_det: 16384 floats

    maf_prep<<<768, 256>>>(W1, b1, W2);              // 64*3072 elements
    maf_main<<<820, 320>>>(z, b2, out_x, out_ld);    // 8200 warps (guarded), 2 rows each
}

// round 4
// speedup vs baseline: 2.8876x; 1.4837x over previous
#include <cuda_runtime.h>
#include <cuda_bf16.h>
#include <math.h>

// Shapes fixed by the problem: B=16384, D=64, H=1024, CLAMP=10.
#define B_ROWS 16384
#define D_DIM  64
#define H_DIM  1024
#define CLAMPV 10.0f
#define NWARPS 10
#define NTHREADS (NWARPS * 32)

// Packed weights, per step i (3072 floats each):
//   [0,1024)    : W1m column i   (masked, m0-sorted)
//   [1024,2048) : W2m row i      (mu row, masked)
//   [2048,3072) : W2m row 64+i   (alpha row, masked)
// Packed index j == sorted position p (identity): warp-contiguous reads.
__device__ __align__(16) float g_w[64 * 3072];
__device__ __align__(16) float g_b1p[H_DIM];

// m0[h] = h % 63 (values 0..62), H sorted stably by m0.
// start_ge(v) = # units with m0 < v.  v in [0,16]: 17/group; else 16.
__host__ __device__ __forceinline__ int start_ge(int v) {
    return (v <= 16) ? 17 * v : 16 * v + 16;
}

__device__ __forceinline__ float tanh_fast(float x) {
    // tanh(x) = 1 - 2/(exp(2x)+1): MUFU EX2 + RCP, ~1e-7 abs error.
    float e = __expf(2.0f * x);
    return 1.0f - __fdividef(2.0f, e + 1.0f);
}

__device__ __forceinline__ void cp16(void* smem_dst, const void* gsrc) {
    unsigned s = (unsigned)__cvta_generic_to_shared(smem_dst);
    asm volatile("cp.async.cg.shared.global [%0], [%1], 16;" :: "r"(s), "l"(gsrc));
}
__device__ __forceinline__ void cp_commit() {
    asm volatile("cp.async.commit_group;" ::: "memory");
}
__device__ __forceinline__ void cp_wait1() {
    asm volatile("cp.async.wait_group 1;" ::: "memory");
}

// ---------------- prep: permute + mask + pack weights ----------------
__global__ void maf_prep(const float* __restrict__ W1,
                         const float* __restrict__ b1,
                         const float* __restrict__ W2) {
    int gid = blockIdx.x * blockDim.x + threadIdx.x;
    if (gid >= 64 * 3072) return;
    int i   = gid / 3072;
    int rem = gid - i * 3072;
    int sec = rem >> 10;        // 0: W1 col, 1: mu row, 2: alpha row
    int p   = rem & 1023;       // packed index == sorted position
    int v, k2;
    if (p < 272) { v = p / 17; k2 = p - v * 17; }
    else         { int r = p - 272; v = 16 + (r >> 4); k2 = r & 15; }
    int h = v + 63 * k2;        // original unit index

    float val;
    if (sec == 0)      val = (i <= v)            ? W1[h * 64 + i]          : 0.0f;
    else if (sec == 1) val = (v < (i >> 1))      ? W2[i * 1024 + h]        : 0.0f;
    else               val = (v < 32 + (i >> 1)) ? W2[(64 + i) * 1024 + h] : 0.0f;
    g_w[gid] = val;

    if (gid < 1024) {
        int pp = gid;
        int vv, kk;
        if (pp < 272) { vv = pp / 17; kk = pp - vv * 17; }
        else          { int r = pp - 272; vv = 16 + (r >> 4); kk = r & 15; }
        g_b1p[gid] = b1[vv + 63 * kk];
    }
}

// ---------------- main: 1 warp = 2 rows, 32 units/lane ----------------
// Weights for the current step staged in smem (3-stage cp.async pipeline,
// one __syncthreads per step keeps the block in lockstep -> L1/LDS hits).
__global__ void __launch_bounds__(NTHREADS) maf_main(
    const float* __restrict__ z, const float* __restrict__ b2,
    float* __restrict__ out_x, float* __restrict__ out_ld)
{
    __shared__ __align__(16) float sw[3][3072];

    const int tid  = threadIdx.x;
    const int l    = tid & 31;
    const int warp = blockIdx.x * NWARPS + (tid >> 5);
    const bool live = (warp < B_ROWS / 2);
    const int wc   = live ? warp : (B_ROWS / 2 - 1);   // clamped (no early exit: barriers)
    const int r0 = wc * 2, r1 = r0 + 1;

    float s0[32], s1[32], t0[32], t1[32];

    // prologue: prefetch steps 0 and 1 into smem
#pragma unroll
    for (int st = 0; st < 2; st++) {
        const float* src = g_w + st * 3072;
        for (int j = tid; j < 768; j += NTHREADS) cp16(&sw[st][j * 4], src + j * 4);
        cp_commit();
    }

    // init s = b1 (x starts at zero), t = tanh(s)
    const float4* b1v = (const float4*)(g_b1p);
#pragma unroll
    for (int kb = 0; kb < 8; kb++) {
        float4 b = b1v[kb * 32 + l];
        s0[4*kb+0] = b.x; s0[4*kb+1] = b.y; s0[4*kb+2] = b.z; s0[4*kb+3] = b.w;
        s1[4*kb+0] = b.x; s1[4*kb+1] = b.y; s1[4*kb+2] = b.z; s1[4*kb+3] = b.w;
    }
#pragma unroll
    for (int k = 0; k < 32; k++) {
        float tv = tanh_fast(s0[k]);
        t0[k] = tv; t1[k] = tv;
    }

    // preload z: lane l holds columns 2l, 2l+1 of each row
    float zA0 = z[r0 * 64 + 2 * l], zA1 = z[r0 * 64 + 2 * l + 1];
    float zB0 = z[r1 * 64 + 2 * l], zB1 = z[r1 * 64 + 2 * l + 1];
    // preload b2: lane l holds b2[2l], b2[2l+1], b2[64+2l], b2[64+2l+1]
    float bmu_lo = b2[2 * l], bmu_hi = b2[2 * l + 1];
    float bal_lo = b2[64 + 2 * l], bal_hi = b2[64 + 2 * l + 1];

    float xlo0 = 0.f, xhi0 = 0.f, xlo1 = 0.f, xhi1 = 0.f;
    float ld0 = 0.f, ld1 = 0.f;

#pragma unroll 1
    for (int i = 0; i < 64; i++) {
        cp_wait1();              // stage i resident (i+1 may still be in flight)
        __syncthreads();         // whole block sees it; prior readers of the
                                 // buffer we are about to refill are done
        if (i + 2 < 64) {        // prefetch step i+2 into buffer (i+2)%3
            const float* src = g_w + (i + 2) * 3072;
            float* dst = sw[(i + 2) % 3];
            for (int j = tid; j < 768; j += NTHREADS) cp16(dst + j * 4, src + j * 4);
        }
        cp_commit();             // always commit (empty groups keep numbering)

        const float* wb = sw[i % 3];
        const float4* w1v  = (const float4*)(wb);
        const float4* wmuv = (const float4*)(wb + 1024);
        const float4* walv = (const float4*)(wb + 2048);

        // dots (masked weights pre-zeroed -> full width, no predication)
        float m0a = 0.f, m0b = 0.f, m1a = 0.f, m1b = 0.f;
        float a0a = 0.f, a0b = 0.f, a1a = 0.f, a1b = 0.f;
#pragma unroll
        for (int kb = 0; kb < 8; kb++) {
            float4 wm = wmuv[kb * 32 + l];
            float4 wa = walv[kb * 32 + l];
            m0a = fmaf(t0[4*kb+0], wm.x, m0a); m0b = fmaf(t0[4*kb+1], wm.y, m0b);
            m0a = fmaf(t0[4*kb+2], wm.z, m0a); m0b = fmaf(t0[4*kb+3], wm.w, m0b);
            m1a = fmaf(t1[4*kb+0], wm.x, m1a); m1b = fmaf(t1[4*kb+1], wm.y, m1b);
            m1a = fmaf(t1[4*kb+2], wm.z, m1a); m1b = fmaf(t1[4*kb+3], wm.w, m1b);
            a0a = fmaf(t0[4*kb+0], wa.x, a0a); a0b = fmaf(t0[4*kb+1], wa.y, a0b);
            a0a = fmaf(t0[4*kb+2], wa.z, a0a); a0b = fmaf(t0[4*kb+3], wa.w, a0b);
            a1a = fmaf(t1[4*kb+0], wa.x, a1a); a1b = fmaf(t1[4*kb+1], wa.y, a1b);
            a1a = fmaf(t1[4*kb+2], wa.z, a1a); a1b = fmaf(t1[4*kb+3], wa.w, a1b);
        }

        float pm0 = m0a + m0b, pa0 = a0a + a0b;
        float pm1 = m1a + m1b, pa1 = a1a + a1b;
#pragma unroll
        for (int off = 16; off; off >>= 1) {
            pm0 += __shfl_xor_sync(0xffffffffu, pm0, off);
            pa0 += __shfl_xor_sync(0xffffffffu, pa0, off);
            pm1 += __shfl_xor_sync(0xffffffffu, pm1, off);
            pa1 += __shfl_xor_sync(0xffffffffu, pa1, off);
        }

        float b2mu = __shfl_sync(0xffffffffu, (i & 1) ? bmu_hi : bmu_lo, i >> 1);
        float b2al = __shfl_sync(0xffffffffu, (i & 1) ? bal_hi : bal_lo, i >> 1);
        float mu0 = fminf(fmaxf(pm0 + b2mu, -CLAMPV), CLAMPV);
        float mu1 = fminf(fmaxf(pm1 + b2mu, -CLAMPV), CLAMPV);
        float aa0 = fminf(fmaxf(pa0 + b2al, -CLAMPV), CLAMPV);
        float aa1 = fminf(fmaxf(pa1 + b2al, -CLAMPV), CLAMPV);

        float zi0 = __shfl_sync(0xffffffffu, (i & 1) ? zA1 : zA0, i >> 1);
        float zi1 = __shfl_sync(0xffffffffu, (i & 1) ? zB1 : zB0, i >> 1);
        float x0 = fmaf(zi0, __expf(aa0), mu0);
        float x1 = fmaf(zi1, __expf(aa1), mu1);
        ld0 += aa0; ld1 += aa1;
        if ((i >> 1) == l) {
            if (i & 1) { xhi0 = x0; xhi1 = x1; }
            else       { xlo0 = x0; xlo1 = x1; }
        }

        // rank-1 update: s += W1m[:,i] * x_i (zero weights mask the suffix)
#pragma unroll
        for (int kb = 0; kb < 8; kb++) {
            float4 w = w1v[kb * 32 + l];
            s0[4*kb+0] = fmaf(w.x, x0, s0[4*kb+0]);
            s0[4*kb+1] = fmaf(w.y, x0, s0[4*kb+1]);
            s0[4*kb+2] = fmaf(w.z, x0, s0[4*kb+2]);
            s0[4*kb+3] = fmaf(w.w, x0, s0[4*kb+3]);
            s1[4*kb+0] = fmaf(w.x, x1, s1[4*kb+0]);
            s1[4*kb+1] = fmaf(w.y, x1, s1[4*kb+1]);
            s1[4*kb+2] = fmaf(w.z, x1, s1[4*kb+2]);
            s1[4*kb+3] = fmaf(w.w, x1, s1[4*kb+3]);
        }

        // lazy tanh refresh on [start_ge(i), start_ge(32+(i+1)/2)),
        // chunk-granular (block kb covers p in [kb*128+4l, +4); over-refresh safe)
        int S  = start_ge(i);
        int v2 = 32 + ((i + 1) >> 1);
        int E2 = start_ge(v2); if (E2 > 1024) E2 = 1024;
#pragma unroll
        for (int kb = 0; kb < 8; kb++) {
            int pb = kb * 128 + l * 4;
            if (pb < E2 && pb + 4 > S) {
                t0[4*kb+0] = tanh_fast(s0[4*kb+0]);
                t0[4*kb+1] = tanh_fast(s0[4*kb+1]);
                t0[4*kb+2] = tanh_fast(s0[4*kb+2]);
                t0[4*kb+3] = tanh_fast(s0[4*kb+3]);
                t1[4*kb+0] = tanh_fast(s1[4*kb+0]);
                t1[4*kb+1] = tanh_fast(s1[4*kb+1]);
                t1[4*kb+2] = tanh_fast(s1[4*kb+2]);
                t1[4*kb+3] = tanh_fast(s1[4*kb+3]);
            }
        }
    }

    // epilogue: NaN/Inf cleanup + stores (guarded; dead warps computed row 8191)
    if (live) {
        if (!isfinite(xlo0)) xlo0 = 0.f;
        if (!isfinite(xhi0)) xhi0 = 0.f;
        if (!isfinite(xlo1)) xlo1 = 0.f;
        if (!isfinite(xhi1)) xhi1 = 0.f;
        out_x[r0 * 64 + 2 * l]     = xlo0;
        out_x[r0 * 64 + 2 * l + 1] = xhi0;
        out_x[r1 * 64 + 2 * l]     = xlo1;
        out_x[r1 * 64 + 2 * l + 1] = xhi1;
        if (l == 0) {
            if (!isfinite(ld0)) ld0 = 0.f;
            if (!isfinite(ld1)) ld1 = 0.f;
            out_ld[r0] = ld0;
            out_ld[r1] = ld1;
        }
    }
}

extern "C" void kernel_launch(void* const* d_in, const int* in_sizes, int n_in,
                              void* d_out, int out_size) {
    const float* z  = (const float*)d_in[0];   // (16384, 64)
    const float* W1 = (const float*)d_in[1];   // (1024, 64)
    const float* b1 = (const float*)d_in[2];   // (1024,)
    const float* W2 = (const float*)d_in[3];   // (128, 1024)
    const float* b2 = (const float*)d_in[4];   // (128,)
    float* out    = (float*)d_out;
    float* out_x  = out;                       // x: 16384*64 floats
    float* out_ld = out + B_ROWS * D_DIM;      // log_det: 16384 floats

    maf_prep<<<768, 256>>>(W1, b1, W2);                   // 64*3072 elements
    int nblocks = (B_ROWS / 2 + NWARPS - 1) / NWARPS;     // 820
    maf_main<<<nblocks, NTHREADS>>>(z, b2, out_x, out_ld);
}

// round 5
// speedup vs baseline: 3.0451x; 1.0545x over previous
#include <cuda_runtime.h>
#include <cuda_bf16.h>
#include <math.h>

// Shapes fixed by the problem: B=16384, D=64, H=1024, CLAMP=10.
#define B_ROWS 16384
#define D_DIM  64
#define H_DIM  1024
#define CLAMPV 10.0f
#define NTHREADS 256      // 8 warps = 4 warp-pairs = 8 rows per block

typedef unsigned long long ull;

// Packed weights, per step i (3072 floats each):
//   [0,1024)    : W1m column i   (masked, m0-sorted)
//   [1024,2048) : W2m row i      (mu row, masked)
//   [2048,3072) : W2m row 64+i   (alpha row, masked)
// Packed index j == sorted position p (identity): warp-contiguous reads.
__device__ __align__(16) float g_w[64 * 3072];
__device__ __align__(16) float g_b1p[H_DIM];

// m0[h] = h % 63 (values 0..62), H sorted stably by m0.
// start_ge(v) = # units with m0 < v.
__host__ __device__ __forceinline__ int start_ge(int v) {
    return (v <= 16) ? 17 * v : 16 * v + 16;
}

__device__ __forceinline__ float tanh_fast(float x) {
    // tanh(x) = 1 - 2/(exp(2x)+1): MUFU EX2 + RCP, ~1e-7 abs error.
    float e = __expf(2.0f * x);
    return 1.0f - __fdividef(2.0f, e + 1.0f);
}

// Blackwell packed f32x2 FMA (only reachable via PTX).
__device__ __forceinline__ ull ffma2(ull a, ull b, ull c) {
    ull d;
    asm("fma.rn.f32x2 %0, %1, %2, %3;" : "=l"(d) : "l"(a), "l"(b), "l"(c));
    return d;
}
__device__ __forceinline__ ull mk2(float lo, float hi) {
    ull r; asm("mov.b64 %0, {%1, %2};" : "=l"(r) : "f"(lo), "f"(hi)); return r;
}
__device__ __forceinline__ void un2(ull u, float& lo, float& hi) {
    asm("mov.b64 {%0, %1}, %2;" : "=f"(lo), "=f"(hi) : "l"(u));
}

__device__ __forceinline__ void cp16(void* smem_dst, const void* gsrc) {
    unsigned s = (unsigned)__cvta_generic_to_shared(smem_dst);
    asm volatile("cp.async.cg.shared.global [%0], [%1], 16;" :: "r"(s), "l"(gsrc));
}
__device__ __forceinline__ void cp_commit() {
    asm volatile("cp.async.commit_group;" ::: "memory");
}
__device__ __forceinline__ void cp_wait1() {
    asm volatile("cp.async.wait_group 1;" ::: "memory");
}

// ---------------- prep: permute + mask + pack weights ----------------
__global__ void maf_prep(const float* __restrict__ W1,
                         const float* __restrict__ b1,
                         const float* __restrict__ W2) {
    int gid = blockIdx.x * blockDim.x + threadIdx.x;
    if (gid >= 64 * 3072) return;
    int i   = gid / 3072;
    int rem = gid - i * 3072;
    int sec = rem >> 10;
    int p   = rem & 1023;
    int v, k2;
    if (p < 272) { v = p / 17; k2 = p - v * 17; }
    else         { int r = p - 272; v = 16 + (r >> 4); k2 = r & 15; }
    int h = v + 63 * k2;

    float val;
    if (sec == 0)      val = (i <= v)            ? W1[h * 64 + i]          : 0.0f;
    else if (sec == 1) val = (v < (i >> 1))      ? W2[i * 1024 + h]        : 0.0f;
    else               val = (v < 32 + (i >> 1)) ? W2[(64 + i) * 1024 + h] : 0.0f;
    g_w[gid] = val;

    if (gid < 1024) {
        int pp = gid;
        int vv, kk;
        if (pp < 272) { vv = pp / 17; kk = pp - vv * 17; }
        else          { int r = pp - 272; vv = 16 + (r >> 4); kk = r & 15; }
        g_b1p[gid] = b1[vv + 63 * kk];
    }
}

// ------------- main: warp-pair = 2 rows, 16 units/lane/warp -------------
// Warp half h covers sorted positions [h*512, (h+1)*512).
// Lane l, chunk kb in [0,4): positions h*512 + kb*128 + l*4 + {0..3},
// stored as 2 f32x2 pairs (indices 2kb, 2kb+1).
__global__ void __launch_bounds__(NTHREADS, 2) maf_main(
    const float* __restrict__ z, const float* __restrict__ b2,
    float* __restrict__ out_x, float* __restrict__ out_ld)
{
    __shared__ __align__(16) float sw[3][3072];
    __shared__ float4 red[4][2];   // per warp-pair: {pm0, pa0, pm1, pa1} per half

    const int tid  = threadIdx.x;
    const int l    = tid & 31;
    const int half = (tid >> 5) & 1;
    const int pr   = tid >> 6;                      // warp-pair in block, 0..3
    const int rowp = blockIdx.x * 4 + pr;           // global row-pair
    const int r0 = rowp * 2, r1 = r0 + 1;
    const int fbase = half * 128;                   // float4-index base of this half

    ull sp0[8], sp1[8], tp0[8], tp1[8];

    // prologue: prefetch steps 0 and 1 into smem
#pragma unroll
    for (int st = 0; st < 2; st++) {
        const float* src = g_w + st * 3072;
        for (int j = tid; j < 768; j += NTHREADS) cp16(&sw[st][j * 4], src + j * 4);
        cp_commit();
    }

    // init s = b1 (x starts at zero), t = tanh(s)
    const float4* b1v = (const float4*)(g_b1p);
#pragma unroll
    for (int kb = 0; kb < 4; kb++) {
        float4 b = b1v[fbase + kb * 32 + l];
        sp0[2*kb]   = mk2(b.x, b.y); sp0[2*kb+1] = mk2(b.z, b.w);
        sp1[2*kb]   = sp0[2*kb];     sp1[2*kb+1] = sp0[2*kb+1];
        tp0[2*kb]   = mk2(tanh_fast(b.x), tanh_fast(b.y));
        tp0[2*kb+1] = mk2(tanh_fast(b.z), tanh_fast(b.w));
        tp1[2*kb]   = tp0[2*kb];     tp1[2*kb+1] = tp0[2*kb+1];
    }

    // preload z and b2 (both warps of a pair hold the same rows)
    float zA0 = z[r0 * 64 + 2 * l], zA1 = z[r0 * 64 + 2 * l + 1];
    float zB0 = z[r1 * 64 + 2 * l], zB1 = z[r1 * 64 + 2 * l + 1];
    float bmu_lo = b2[2 * l], bmu_hi = b2[2 * l + 1];
    float bal_lo = b2[64 + 2 * l], bal_hi = b2[64 + 2 * l + 1];

    float xlo0 = 0.f, xhi0 = 0.f, xlo1 = 0.f, xhi1 = 0.f;
    float ld0 = 0.f, ld1 = 0.f;

#pragma unroll 1
    for (int i = 0; i < 64; i++) {
        cp_wait1();
        __syncthreads();          // stage i visible; red[] reads of step i-1 done
        if (i + 2 < 64) {
            const float* src = g_w + (i + 2) * 3072;
            float* dst = sw[(i + 2) % 3];
            for (int j = tid; j < 768; j += NTHREADS) cp16(dst + j * 4, src + j * 4);
        }
        cp_commit();

        const float* wb = sw[i % 3];
        const float4* w1v  = (const float4*)(wb);
        const float4* wmuv = (const float4*)(wb + 1024);
        const float4* walv = (const float4*)(wb + 2048);

        // dots over this half's 512 units, f32x2-packed, 8 accumulator chains
        ull am0a = 0ull, am0b = 0ull, am1a = 0ull, am1b = 0ull;
        ull aa0a = 0ull, aa0b = 0ull, aa1a = 0ull, aa1b = 0ull;
#pragma unroll
        for (int kb = 0; kb < 4; kb++) {
            float4 wmf = wmuv[fbase + kb * 32 + l];
            float4 waf = walv[fbase + kb * 32 + l];
            ull wm01 = mk2(wmf.x, wmf.y), wm23 = mk2(wmf.z, wmf.w);
            ull wa01 = mk2(waf.x, waf.y), wa23 = mk2(waf.z, waf.w);
            am0a = ffma2(tp0[2*kb],   wm01, am0a);
            am0b = ffma2(tp0[2*kb+1], wm23, am0b);
            am1a = ffma2(tp1[2*kb],   wm01, am1a);
            am1b = ffma2(tp1[2*kb+1], wm23, am1b);
            aa0a = ffma2(tp0[2*kb],   wa01, aa0a);
            aa0b = ffma2(tp0[2*kb+1], wa23, aa0b);
            aa1a = ffma2(tp1[2*kb],   wa01, aa1a);
            aa1b = ffma2(tp1[2*kb+1], wa23, aa1b);
        }
        float u, v_;
        float pm0, pa0, pm1, pa1;
        un2(am0a, u, v_); pm0 = u + v_; un2(am0b, u, v_); pm0 += u + v_;
        un2(am1a, u, v_); pm1 = u + v_; un2(am1b, u, v_); pm1 += u + v_;
        un2(aa0a, u, v_); pa0 = u + v_; un2(aa0b, u, v_); pa0 += u + v_;
        un2(aa1a, u, v_); pa1 = u + v_; un2(aa1b, u, v_); pa1 += u + v_;

#pragma unroll
        for (int off = 16; off; off >>= 1) {
            pm0 += __shfl_xor_sync(0xffffffffu, pm0, off);
            pa0 += __shfl_xor_sync(0xffffffffu, pa0, off);
            pm1 += __shfl_xor_sync(0xffffffffu, pm1, off);
            pa1 += __shfl_xor_sync(0xffffffffu, pa1, off);
        }
        if (l == 0) red[pr][half] = make_float4(pm0, pa0, pm1, pa1);
        __syncthreads();
        float4 oth = red[pr][1 - half];
        pm0 += oth.x; pa0 += oth.y; pm1 += oth.z; pa1 += oth.w;

        float b2mu = __shfl_sync(0xffffffffu, (i & 1) ? bmu_hi : bmu_lo, i >> 1);
        float b2al = __shfl_sync(0xffffffffu, (i & 1) ? bal_hi : bal_lo, i >> 1);
        float mu0 = fminf(fmaxf(pm0 + b2mu, -CLAMPV), CLAMPV);
        float mu1 = fminf(fmaxf(pm1 + b2mu, -CLAMPV), CLAMPV);
        float aa0 = fminf(fmaxf(pa0 + b2al, -CLAMPV), CLAMPV);
        float aa1 = fminf(fmaxf(pa1 + b2al, -CLAMPV), CLAMPV);

        float zi0 = __shfl_sync(0xffffffffu, (i & 1) ? zA1 : zA0, i >> 1);
        float zi1 = __shfl_sync(0xffffffffu, (i & 1) ? zB1 : zB0, i >> 1);
        float x0 = fmaf(zi0, __expf(aa0), mu0);
        float x1 = fmaf(zi1, __expf(aa1), mu1);
        ld0 += aa0; ld1 += aa1;
        if ((i >> 1) == l) {
            if (i & 1) { xhi0 = x0; xhi1 = x1; }
            else       { xlo0 = x0; xlo1 = x1; }
        }

        // rank-1 update: s += W1m[:,i] * x_i (zero weights mask the suffix)
        ull xx0 = mk2(x0, x0), xx1 = mk2(x1, x1);
#pragma unroll
        for (int kb = 0; kb < 4; kb++) {
            float4 wf = w1v[fbase + kb * 32 + l];
            ull w01 = mk2(wf.x, wf.y), w23 = mk2(wf.z, wf.w);
            sp0[2*kb]   = ffma2(w01, xx0, sp0[2*kb]);
            sp0[2*kb+1] = ffma2(w23, xx0, sp0[2*kb+1]);
            sp1[2*kb]   = ffma2(w01, xx1, sp1[2*kb]);
            sp1[2*kb+1] = ffma2(w23, xx1, sp1[2*kb+1]);
        }

        // lazy tanh refresh on [start_ge(i), start_ge(32+(i+1)/2)), chunk-granular
        int S  = start_ge(i);
        int v2 = 32 + ((i + 1) >> 1);
        int E2 = start_ge(v2); if (E2 > 1024) E2 = 1024;
#pragma unroll
        for (int kb = 0; kb < 4; kb++) {
            int pb = half * 512 + kb * 128 + l * 4;
            if (pb < E2 && pb + 4 > S) {
                float a0, a1_, b0, b1_;
                un2(sp0[2*kb], a0, a1_);   tp0[2*kb]   = mk2(tanh_fast(a0), tanh_fast(a1_));
                un2(sp0[2*kb+1], b0, b1_); tp0[2*kb+1] = mk2(tanh_fast(b0), tanh_fast(b1_));
                un2(sp1[2*kb], a0, a1_);   tp1[2*kb]   = mk2(tanh_fast(a0), tanh_fast(a1_));
                un2(sp1[2*kb+1], b0, b1_); tp1[2*kb+1] = mk2(tanh_fast(b0), tanh_fast(b1_));
            }
        }
    }

    // epilogue: half 0 stores (both halves computed identical x / log_det)
    if (half == 0) {
        if (!isfinite(xlo0)) xlo0 = 0.f;
        if (!isfinite(xhi0)) xhi0 = 0.f;
        if (!isfinite(xlo1)) xlo1 = 0.f;
        if (!isfinite(xhi1)) xhi1 = 0.f;
        out_x[r0 * 64 + 2 * l]     = xlo0;
        out_x[r0 * 64 + 2 * l + 1] = xhi0;
        out_x[r1 * 64 + 2 * l]     = xlo1;
        out_x[r1 * 64 + 2 * l + 1] = xhi1;
        if (l == 0) {
            if (!isfinite(ld0)) ld0 = 0.f;
            if (!isfinite(ld1)) ld1 = 0.f;
            out_ld[r0] = ld0;
            out_ld[r1] = ld1;
        }
    }
}

extern "C" void kernel_launch(void* const* d_in, const int* in_sizes, int n_in,
                              void* d_out, int out_size) {
    const float* z  = (const float*)d_in[0];   // (16384, 64)
    const float* W1 = (const float*)d_in[1];   // (1024, 64)
    const float* b1 = (const float*)d_in[2];   // (1024,)
    const float* W2 = (const float*)d_in[3];   // (128, 1024)
    const float* b2 = (const float*)d_in[4];   // (128,)
    float* out    = (float*)d_out;
    float* out_x  = out;                       // x: 16384*64 floats
    float* out_ld = out + B_ROWS * D_DIM;      // log_det: 16384 floats

    maf_prep<<<768, 256>>>(W1, b1, W2);        // 64*3072 elements
    // 8 rows per block -> 2048 blocks; 2 blocks/SM (16 warps/SM)
    maf_main<<<B_ROWS / 8, NTHREADS>>>(z, b2, out_x, out_ld);
}

// round 6
// speedup vs baseline: 3.5706x; 1.1726x over previous
#include <cuda_runtime.h>
#include <cuda_bf16.h>
#include <math.h>

// Shapes fixed by the problem: B=16384, D=64, H=1024, CLAMP=10.
#define B_ROWS 16384
#define D_DIM  64
#define H_DIM  1024
#define CLAMPV 10.0f
#define NTHREADS 256      // 8 warps = 4 warp-pairs = 8 rows per block

typedef unsigned long long ull;

// Packed weights, per step i (3072 floats each):
//   [0,1024)    : W1m column i   (masked, m0-sorted)
//   [1024,2048) : W2m row i      (mu row, masked)
//   [2048,3072) : W2m row 64+i   (alpha row, masked)
__device__ __align__(16) float g_w[64 * 3072];
__device__ __align__(16) float g_b1p[H_DIM];

// m0[h] = h % 63 (values 0..62), H sorted stably by m0.
__host__ __device__ __forceinline__ int start_ge(int v) {
    return (v <= 16) ? 17 * v : 16 * v + 16;
}

__device__ __forceinline__ float tanh_mufu(float x) {
    float y; asm("tanh.approx.f32 %0, %1;" : "=f"(y) : "f"(x)); return y;
}

// Blackwell packed f32x2 FMA (PTX-only).
__device__ __forceinline__ ull ffma2(ull a, ull b, ull c) {
    ull d;
    asm("fma.rn.f32x2 %0, %1, %2, %3;" : "=l"(d) : "l"(a), "l"(b), "l"(c));
    return d;
}
__device__ __forceinline__ ull mk2(float lo, float hi) {
    ull r; asm("mov.b64 %0, {%1, %2};" : "=l"(r) : "f"(lo), "f"(hi)); return r;
}
__device__ __forceinline__ void un2(ull u, float& lo, float& hi) {
    asm("mov.b64 {%0, %1}, %2;" : "=f"(lo), "=f"(hi) : "l"(u));
}
// 16B smem load straight into two f32x2 operands (no packing movs).
__device__ __forceinline__ void lds2(ull& a, ull& b, unsigned addr) {
    asm volatile("ld.shared.v2.u64 {%0, %1}, [%2];" : "=l"(a), "=l"(b) : "r"(addr));
}

__device__ __forceinline__ void cp16(void* smem_dst, const void* gsrc) {
    unsigned s = (unsigned)__cvta_generic_to_shared(smem_dst);
    asm volatile("cp.async.cg.shared.global [%0], [%1], 16;" :: "r"(s), "l"(gsrc));
}
__device__ __forceinline__ void cp_commit() {
    asm volatile("cp.async.commit_group;" ::: "memory");
}
__device__ __forceinline__ void cp_wait1() {
    asm volatile("cp.async.wait_group 1;" ::: "memory");
}

// ---------------- prep: permute + mask + pack weights ----------------
__global__ void maf_prep(const float* __restrict__ W1,
                         const float* __restrict__ b1,
                         const float* __restrict__ W2) {
    int gid = blockIdx.x * blockDim.x + threadIdx.x;
    if (gid >= 64 * 3072) return;
    int i   = gid / 3072;
    int rem = gid - i * 3072;
    int sec = rem >> 10;
    int p   = rem & 1023;
    int v, k2;
    if (p < 272) { v = p / 17; k2 = p - v * 17; }
    else         { int r = p - 272; v = 16 + (r >> 4); k2 = r & 15; }
    int h = v + 63 * k2;

    float val;
    if (sec == 0)      val = (i <= v)            ? W1[h * 64 + i]          : 0.0f;
    else if (sec == 1) val = (v < (i >> 1))      ? W2[i * 1024 + h]        : 0.0f;
    else               val = (v < 32 + (i >> 1)) ? W2[(64 + i) * 1024 + h] : 0.0f;
    g_w[gid] = val;

    if (gid < 1024) {
        int pp = gid;
        int vv, kk;
        if (pp < 272) { vv = pp / 17; kk = pp - vv * 17; }
        else          { int r = pp - 272; vv = 16 + (r >> 4); kk = r & 15; }
        g_b1p[gid] = b1[vv + 63 * kk];
    }
}

// ------------- main: warp-pair = 2 rows, 16 units/lane/warp -------------
// Warp half h covers sorted positions [h*512, (h+1)*512).
// Single __syncthreads per step: publishes cp.async stage i+1 AND the
// red[] dot exchange (double-buffered by step parity).
__global__ void __launch_bounds__(NTHREADS, 2) maf_main(
    const float* __restrict__ z, const float* __restrict__ b2,
    float* __restrict__ out_x, float* __restrict__ out_ld)
{
    __shared__ __align__(16) float sw[3][3072];
    __shared__ float4 red[2][4][2];  // [step parity][warp-pair][half]

    const int tid  = threadIdx.x;
    const int l    = tid & 31;
    const int half = (tid >> 5) & 1;
    const int pr   = tid >> 6;                      // warp-pair in block, 0..3
    const int rowp = blockIdx.x * 4 + pr;
    const int r0 = rowp * 2, r1 = r0 + 1;
    const unsigned laneoff = (unsigned)((half * 512 + l * 4) * 4); // byte offset

    ull sp0[8], sp1[8], tp0[8], tp1[8];

    // prologue: prefetch steps 0 and 1 into smem
#pragma unroll
    for (int st = 0; st < 2; st++) {
        const float* src = g_w + st * 3072;
        for (int j = tid; j < 768; j += NTHREADS) cp16(&sw[st][j * 4], src + j * 4);
        cp_commit();
    }

    // init s = b1 (x starts at zero), t = tanh(s)
    const float4* b1v = (const float4*)(g_b1p);
#pragma unroll
    for (int kb = 0; kb < 4; kb++) {
        float4 b = b1v[half * 128 + kb * 32 + l];
        sp0[2*kb]   = mk2(b.x, b.y); sp0[2*kb+1] = mk2(b.z, b.w);
        sp1[2*kb]   = sp0[2*kb];     sp1[2*kb+1] = sp0[2*kb+1];
        tp0[2*kb]   = mk2(tanh_mufu(b.x), tanh_mufu(b.y));
        tp0[2*kb+1] = mk2(tanh_mufu(b.z), tanh_mufu(b.w));
        tp1[2*kb]   = tp0[2*kb];     tp1[2*kb+1] = tp0[2*kb+1];
    }

    // preload z and b2 (both warps of a pair hold the same rows)
    float zA0 = z[r0 * 64 + 2 * l], zA1 = z[r0 * 64 + 2 * l + 1];
    float zB0 = z[r1 * 64 + 2 * l], zB1 = z[r1 * 64 + 2 * l + 1];
    float bmu_lo = b2[2 * l], bmu_hi = b2[2 * l + 1];
    float bal_lo = b2[64 + 2 * l], bal_hi = b2[64 + 2 * l + 1];

    float xlo0 = 0.f, xhi0 = 0.f, xlo1 = 0.f, xhi1 = 0.f;
    float ld0 = 0.f, ld1 = 0.f;

    cp_wait1();          // stage 0 resident
    __syncthreads();     // publish stage 0

#pragma unroll 1
    for (int i = 0; i < 64; i++) {
        const unsigned swb = (unsigned)__cvta_generic_to_shared(sw[i % 3]) + laneoff;

        // --- load W1 column chunk (held across barrier for the update) ---
        ull w01[4], w23[4];
#pragma unroll
        for (int kb = 0; kb < 4; kb++) lds2(w01[kb], w23[kb], swb + kb * 512);

        // --- dots over this half's 512 units (weights consumed immediately) ---
        ull am0 = 0ull, bm0 = 0ull, am1 = 0ull, bm1 = 0ull;
        ull aa0 = 0ull, ba0 = 0ull, aa1 = 0ull, ba1 = 0ull;
#pragma unroll
        for (int kb = 0; kb < 4; kb++) {
            ull wm01, wm23, wa01, wa23;
            lds2(wm01, wm23, swb + 4096 + kb * 512);
            lds2(wa01, wa23, swb + 8192 + kb * 512);
            am0 = ffma2(tp0[2*kb],   wm01, am0);
            bm0 = ffma2(tp0[2*kb+1], wm23, bm0);
            am1 = ffma2(tp1[2*kb],   wm01, am1);
            bm1 = ffma2(tp1[2*kb+1], wm23, bm1);
            aa0 = ffma2(tp0[2*kb],   wa01, aa0);
            ba0 = ffma2(tp0[2*kb+1], wa23, ba0);
            aa1 = ffma2(tp1[2*kb],   wa01, aa1);
            ba1 = ffma2(tp1[2*kb+1], wa23, ba1);
        }
        float u, v_;
        float pm0, pa0, pm1, pa1;
        un2(am0, u, v_); pm0 = u + v_; un2(bm0, u, v_); pm0 += u + v_;
        un2(am1, u, v_); pm1 = u + v_; un2(bm1, u, v_); pm1 += u + v_;
        un2(aa0, u, v_); pa0 = u + v_; un2(ba0, u, v_); pa0 += u + v_;
        un2(aa1, u, v_); pa1 = u + v_; un2(ba1, u, v_); pa1 += u + v_;

#pragma unroll
        for (int off = 16; off; off >>= 1) {
            pm0 += __shfl_xor_sync(0xffffffffu, pm0, off);
            pa0 += __shfl_xor_sync(0xffffffffu, pa0, off);
            pm1 += __shfl_xor_sync(0xffffffffu, pm1, off);
            pa1 += __shfl_xor_sync(0xffffffffu, pa1, off);
        }
        if (l == 0) red[i & 1][pr][half] = make_float4(pm0, pa0, pm1, pa1);

        // --- prefetch stage i+2 (overwrites stage (i-1)%3: its readers loaded
        //     their regs before the barrier of step i-1) ---
        if (i + 2 < 64) {
            const float* src = g_w + (i + 2) * 3072;
            float* dst = sw[(i + 2) % 3];
            for (int j = tid; j < 768; j += NTHREADS) cp16(dst + j * 4, src + j * 4);
        }
        cp_commit();
        cp_wait1();          // stage i+1 resident
        __syncthreads();     // publish stage i+1 + red[] exchange

        // --- cross-warp combine + scalar tail ---
        float4 oth = red[i & 1][pr][1 - half];
        pm0 += oth.x; pa0 += oth.y; pm1 += oth.z; pa1 += oth.w;

        float b2mu = __shfl_sync(0xffffffffu, (i & 1) ? bmu_hi : bmu_lo, i >> 1);
        float b2al = __shfl_sync(0xffffffffu, (i & 1) ? bal_hi : bal_lo, i >> 1);
        float mu0 = fminf(fmaxf(pm0 + b2mu, -CLAMPV), CLAMPV);
        float mu1 = fminf(fmaxf(pm1 + b2mu, -CLAMPV), CLAMPV);
        float aA0 = fminf(fmaxf(pa0 + b2al, -CLAMPV), CLAMPV);
        float aA1 = fminf(fmaxf(pa1 + b2al, -CLAMPV), CLAMPV);

        float zi0 = __shfl_sync(0xffffffffu, (i & 1) ? zA1 : zA0, i >> 1);
        float zi1 = __shfl_sync(0xffffffffu, (i & 1) ? zB1 : zB0, i >> 1);
        float x0 = fmaf(zi0, __expf(aA0), mu0);
        float x1 = fmaf(zi1, __expf(aA1), mu1);
        ld0 += aA0; ld1 += aA1;
        if ((i >> 1) == l) {
            if (i & 1) { xhi0 = x0; xhi1 = x1; }
            else       { xlo0 = x0; xlo1 = x1; }
        }

        // --- rank-1 update (register-held W1; zero weights mask the suffix) ---
        ull xx0 = mk2(x0, x0), xx1 = mk2(x1, x1);
#pragma unroll
        for (int kb = 0; kb < 4; kb++) {
            sp0[2*kb]   = ffma2(w01[kb], xx0, sp0[2*kb]);
            sp0[2*kb+1] = ffma2(w23[kb], xx0, sp0[2*kb+1]);
            sp1[2*kb]   = ffma2(w01[kb], xx1, sp1[2*kb]);
            sp1[2*kb+1] = ffma2(w23[kb], xx1, sp1[2*kb+1]);
        }

        // --- lazy tanh refresh on [start_ge(i), start_ge(32+(i+1)/2)) ---
        int S  = start_ge(i);
        int v2 = 32 + ((i + 1) >> 1);
        int E2 = start_ge(v2); if (E2 > 1024) E2 = 1024;
#pragma unroll
        for (int kb = 0; kb < 4; kb++) {
            int pb = half * 512 + kb * 128 + l * 4;
            if (pb < E2 && pb + 4 > S) {
                float a0, a1_, c0, c1;
                un2(sp0[2*kb], a0, a1_);   tp0[2*kb]   = mk2(tanh_mufu(a0), tanh_mufu(a1_));
                un2(sp0[2*kb+1], c0, c1);  tp0[2*kb+1] = mk2(tanh_mufu(c0), tanh_mufu(c1));
                un2(sp1[2*kb], a0, a1_);   tp1[2*kb]   = mk2(tanh_mufu(a0), tanh_mufu(a1_));
                un2(sp1[2*kb+1], c0, c1);  tp1[2*kb+1] = mk2(tanh_mufu(c0), tanh_mufu(c1));
            }
        }
    }

    // epilogue: half 0 stores (both halves computed identical x / log_det)
    if (half == 0) {
        if (!isfinite(xlo0)) xlo0 = 0.f;
        if (!isfinite(xhi0)) xhi0 = 0.f;
        if (!isfinite(xlo1)) xlo1 = 0.f;
        if (!isfinite(xhi1)) xhi1 = 0.f;
        out_x[r0 * 64 + 2 * l]     = xlo0;
        out_x[r0 * 64 + 2 * l + 1] = xhi0;
        out_x[r1 * 64 + 2 * l]     = xlo1;
        out_x[r1 * 64 + 2 * l + 1] = xhi1;
        if (l == 0) {
            if (!isfinite(ld0)) ld0 = 0.f;
            if (!isfinite(ld1)) ld1 = 0.f;
            out_ld[r0] = ld0;
            out_ld[r1] = ld1;
        }
    }
}

extern "C" void kernel_launch(void* const* d_in, const int* in_sizes, int n_in,
                              void* d_out, int out_size) {
    const float* z  = (const float*)d_in[0];   // (16384, 64)
    const float* W1 = (const float*)d_in[1];   // (1024, 64)
    const float* b1 = (const float*)d_in[2];   // (1024,)
    const float* W2 = (const float*)d_in[3];   // (128, 1024)
    const float* b2 = (const float*)d_in[4];   // (128,)
    float* out    = (float*)d_out;
    float* out_x  = out;                       // x: 16384*64 floats
    float* out_ld = out + B_ROWS * D_DIM;      // log_det: 16384 floats

    maf_prep<<<768, 256>>>(W1, b1, W2);
    maf_main<<<B_ROWS / 8, NTHREADS>>>(z, b2, out_x, out_ld);
}

// round 7
// speedup vs baseline: 4.3545x; 1.2195x over previous
#include <cuda_runtime.h>
#include <cuda_bf16.h>
#include <math.h>

// Shapes fixed by the problem: B=16384, D=64, H=1024, CLAMP=10.
#define B_ROWS 16384
#define D_DIM  64
#define H_DIM  1024
#define CLAMPV 10.0f
#define NTHREADS 256      // 8 warps = 4 warp-pairs = 8 rows per block

typedef unsigned long long ull;

// Packed weights, per step i (3072 floats each):
//   [0,1024)    : W1m column i   (masked, m0-sorted)
//   [1024,2048) : W2m row i      (mu row, masked)
//   [2048,3072) : W2m row 64+i   (alpha row, masked)
__device__ __align__(16) float g_w[64 * 3072];
__device__ __align__(16) float g_b1p[H_DIM];

// m0[h] = h % 63 (values 0..62), H sorted stably by m0.
__host__ __device__ __forceinline__ int start_ge(int v) {
    return (v <= 16) ? 17 * v : 16 * v + 16;
}

__device__ __forceinline__ float tanh_mufu(float x) {
    float y; asm("tanh.approx.f32 %0, %1;" : "=f"(y) : "f"(x)); return y;
}

// Blackwell packed f32x2 FMA (PTX-only).
__device__ __forceinline__ ull ffma2(ull a, ull b, ull c) {
    ull d;
    asm("fma.rn.f32x2 %0, %1, %2, %3;" : "=l"(d) : "l"(a), "l"(b), "l"(c));
    return d;
}
__device__ __forceinline__ ull mk2(float lo, float hi) {
    ull r; asm("mov.b64 %0, {%1, %2};" : "=l"(r) : "f"(lo), "f"(hi)); return r;
}
__device__ __forceinline__ void un2(ull u, float& lo, float& hi) {
    asm("mov.b64 {%0, %1}, %2;" : "=f"(lo), "=f"(hi) : "l"(u));
}
// 16B smem load straight into two f32x2 operands.
__device__ __forceinline__ void lds2(ull& a, ull& b, unsigned addr) {
    asm volatile("ld.shared.v2.u64 {%0, %1}, [%2];" : "=l"(a), "=l"(b) : "r"(addr));
}

__device__ __forceinline__ void cp16(unsigned smem_dst, const void* gsrc) {
    asm volatile("cp.async.cg.shared.global [%0], [%1], 16;" :: "r"(smem_dst), "l"(gsrc));
}
__device__ __forceinline__ void cp_commit() {
    asm volatile("cp.async.commit_group;" ::: "memory");
}
__device__ __forceinline__ void cp_wait1() {
    asm volatile("cp.async.wait_group 1;" ::: "memory");
}

// ---------------- prep: permute + mask + pack weights ----------------
__global__ void maf_prep(const float* __restrict__ W1,
                         const float* __restrict__ b1,
                         const float* __restrict__ W2) {
    int gid = blockIdx.x * blockDim.x + threadIdx.x;
    if (gid >= 64 * 3072) return;
    int i   = gid / 3072;
    int rem = gid - i * 3072;
    int sec = rem >> 10;
    int p   = rem & 1023;
    int v, k2;
    if (p < 272) { v = p / 17; k2 = p - v * 17; }
    else         { int r = p - 272; v = 16 + (r >> 4); k2 = r & 15; }
    int h = v + 63 * k2;

    float val;
    if (sec == 0)      val = (i <= v)            ? W1[h * 64 + i]          : 0.0f;
    else if (sec == 1) val = (v < (i >> 1))      ? W2[i * 1024 + h]        : 0.0f;
    else               val = (v < 32 + (i >> 1)) ? W2[(64 + i) * 1024 + h] : 0.0f;
    g_w[gid] = val;

    if (gid < 1024) {
        int pp = gid;
        int vv, kk;
        if (pp < 272) { vv = pp / 17; kk = pp - vv * 17; }
        else          { int r = pp - 272; vv = 16 + (r >> 4); kk = r & 15; }
        g_b1p[gid] = b1[vv + 63 * kk];
    }
}

// ------------- main: warp-pair = 2 rows, 16 units/lane/warp -------------
// Warp half h covers sorted positions [h*512, (h+1)*512).
// One __syncthreads per step: publishes cp.async stage i+1 AND the
// sred[] dot exchange (double-buffered by step parity).
__global__ void __launch_bounds__(NTHREADS, 2) maf_main(
    const float* __restrict__ z, const float* __restrict__ b2,
    float* __restrict__ out_x, float* __restrict__ out_ld)
{
    __shared__ __align__(16) float sw[3][3072];
    __shared__ __align__(16) float sred[2][4][8];  // [parity][pair][class: m0,m1,a0,a1 x half]

    const int tid  = threadIdx.x;
    const int l    = tid & 31;
    const int half = (tid >> 5) & 1;
    const int pr   = tid >> 6;                      // warp-pair in block, 0..3
    const int rowp = blockIdx.x * 4 + pr;
    const int r0 = rowp * 2, r1 = r0 + 1;
    const unsigned laneoff = (unsigned)((half * 512 + l * 4) * 4); // byte offset

    // rotating stage base addresses (byte smem addresses)
    unsigned swA = (unsigned)__cvta_generic_to_shared(&sw[0][0]);
    unsigned sw0 = swA, sw1 = swA + 12288, sw2 = swA + 24576;

    ull sp0[8], sp1[8], tp0[8], tp1[8];

    // prologue: prefetch steps 0 and 1
    {
        const float* s0 = g_w + tid * 4;
        cp16(sw0 + tid * 16,        s0);
        cp16(sw0 + tid * 16 + 4096, s0 + 1024);
        cp16(sw0 + tid * 16 + 8192, s0 + 2048);
        cp_commit();
        const float* s1 = g_w + 3072 + tid * 4;
        cp16(sw1 + tid * 16,        s1);
        cp16(sw1 + tid * 16 + 4096, s1 + 1024);
        cp16(sw1 + tid * 16 + 8192, s1 + 2048);
        cp_commit();
    }
    const float* srcp = g_w + 2 * 3072 + tid * 4;   // stage-(i+2) source

    // init s = b1 (x starts at zero), t = tanh(s)
    const float4* b1v = (const float4*)(g_b1p);
#pragma unroll
    for (int kb = 0; kb < 4; kb++) {
        float4 b = b1v[half * 128 + kb * 32 + l];
        sp0[2*kb]   = mk2(b.x, b.y); sp0[2*kb+1] = mk2(b.z, b.w);
        sp1[2*kb]   = sp0[2*kb];     sp1[2*kb+1] = sp0[2*kb+1];
        tp0[2*kb]   = mk2(tanh_mufu(b.x), tanh_mufu(b.y));
        tp0[2*kb+1] = mk2(tanh_mufu(b.z), tanh_mufu(b.w));
        tp1[2*kb]   = tp0[2*kb];     tp1[2*kb+1] = tp0[2*kb+1];
    }

    // preload z and b2 (both warps of a pair hold the same rows)
    float zA0 = z[r0 * 64 + 2 * l], zA1 = z[r0 * 64 + 2 * l + 1];
    float zB0 = z[r1 * 64 + 2 * l], zB1 = z[r1 * 64 + 2 * l + 1];
    float bmu_lo = b2[2 * l], bmu_hi = b2[2 * l + 1];
    float bal_lo = b2[64 + 2 * l], bal_hi = b2[64 + 2 * l + 1];

    float xlo0 = 0.f, xhi0 = 0.f, xlo1 = 0.f, xhi1 = 0.f;
    float ld0 = 0.f, ld1 = 0.f;

    cp_wait1();          // stage 0 resident
    __syncthreads();     // publish stage 0

#pragma unroll 1
    for (int i = 0; i < 64; i++) {
        const unsigned swb = sw0 + laneoff;

        // --- W1 column chunk (held in regs across barrier for the update) ---
        ull w01[4], w23[4];
#pragma unroll
        for (int kb = 0; kb < 4; kb++) lds2(w01[kb], w23[kb], swb + kb * 512);

        // --- dots over this half's 512 units ---
        ull am0 = 0ull, bm0 = 0ull, am1 = 0ull, bm1 = 0ull;
        ull aa0 = 0ull, ba0 = 0ull, aa1 = 0ull, ba1 = 0ull;
#pragma unroll
        for (int kb = 0; kb < 4; kb++) {
            ull wm01, wm23, wa01, wa23;
            lds2(wm01, wm23, swb + 4096 + kb * 512);
            lds2(wa01, wa23, swb + 8192 + kb * 512);
            am0 = ffma2(tp0[2*kb],   wm01, am0);
            bm0 = ffma2(tp0[2*kb+1], wm23, bm0);
            am1 = ffma2(tp1[2*kb],   wm01, am1);
            bm1 = ffma2(tp1[2*kb+1], wm23, bm1);
            aa0 = ffma2(tp0[2*kb],   wa01, aa0);
            ba0 = ffma2(tp0[2*kb+1], wa23, ba0);
            aa1 = ffma2(tp1[2*kb],   wa01, aa1);
            ba1 = ffma2(tp1[2*kb+1], wa23, ba1);
        }
        float u, v_;
        float pm0, pa0, pm1, pa1;
        un2(am0, u, v_); pm0 = u + v_; un2(bm0, u, v_); pm0 += u + v_;
        un2(am1, u, v_); pm1 = u + v_; un2(bm1, u, v_); pm1 += u + v_;
        un2(aa0, u, v_); pa0 = u + v_; un2(ba0, u, v_); pa0 += u + v_;
        un2(aa1, u, v_); pa1 = u + v_; un2(ba1, u, v_); pa1 += u + v_;

        // --- role-rotation reduction: 6 SHFL for 4 values ---
        // level 1 (off=1): keep class m_{b0} / a_{b0}, give the other
        {
            bool b0 = (l & 1);
            float gm = b0 ? pm0 : pm1, km = b0 ? pm1 : pm0;
            km += __shfl_xor_sync(0xffffffffu, gm, 1);
            float ga = b0 ? pa0 : pa1, ka = b0 ? pa1 : pa0;
            ka += __shfl_xor_sync(0xffffffffu, ga, 1);
            // level 2 (off=2): keep m-class (b1=0) or a-class (b1=1)
            bool bb = (l & 2);
            float g2 = bb ? km : ka, k2 = bb ? ka : km;
            k2 += __shfl_xor_sync(0xffffffffu, g2, 2);
            // levels 3-5: plain butterfly within same class (l&3)
            k2 += __shfl_xor_sync(0xffffffffu, k2, 4);
            k2 += __shfl_xor_sync(0xffffffffu, k2, 8);
            k2 += __shfl_xor_sync(0xffffffffu, k2, 16);
            // lane l<4 publishes class l: 0=m0, 1=m1, 2=a0, 3=a1
            if (l < 4) sred[i & 1][pr][half * 4 + l] = k2;
        }

        // --- prefetch stage i+2 into sw2 ---
        if (i + 2 < 64) {
            cp16(sw2 + tid * 16,        srcp);
            cp16(sw2 + tid * 16 + 4096, srcp + 1024);
            cp16(sw2 + tid * 16 + 8192, srcp + 2048);
            srcp += 3072;
        }
        cp_commit();
        cp_wait1();          // stage i+1 resident
        __syncthreads();     // publish stage i+1 + sred exchange

        // --- combine halves + scalar tail ---
        float4 h0 = *(const float4*)&sred[i & 1][pr][0];
        float4 h1 = *(const float4*)&sred[i & 1][pr][4];
        float fm0 = h0.x + h1.x, fm1 = h0.y + h1.y;
        float fa0 = h0.z + h1.z, fa1 = h0.w + h1.w;

        float b2mu = __shfl_sync(0xffffffffu, (i & 1) ? bmu_hi : bmu_lo, i >> 1);
        float b2al = __shfl_sync(0xffffffffu, (i & 1) ? bal_hi : bal_lo, i >> 1);
        float mu0 = fminf(fmaxf(fm0 + b2mu, -CLAMPV), CLAMPV);
        float mu1 = fminf(fmaxf(fm1 + b2mu, -CLAMPV), CLAMPV);
        float aA0 = fminf(fmaxf(fa0 + b2al, -CLAMPV), CLAMPV);
        float aA1 = fminf(fmaxf(fa1 + b2al, -CLAMPV), CLAMPV);

        float zi0 = __shfl_sync(0xffffffffu, (i & 1) ? zA1 : zA0, i >> 1);
        float zi1 = __shfl_sync(0xffffffffu, (i & 1) ? zB1 : zB0, i >> 1);
        float x0 = fmaf(zi0, __expf(aA0), mu0);
        float x1 = fmaf(zi1, __expf(aA1), mu1);
        ld0 += aA0; ld1 += aA1;
        if ((i >> 1) == l) {
            if (i & 1) { xhi0 = x0; xhi1 = x1; }
            else       { xlo0 = x0; xlo1 = x1; }
        }

        // --- rank-1 update (register-held W1; zeros mask the suffix) ---
        ull xx0 = mk2(x0, x0), xx1 = mk2(x1, x1);
#pragma unroll
        for (int kb = 0; kb < 4; kb++) {
            sp0[2*kb]   = ffma2(w01[kb], xx0, sp0[2*kb]);
            sp0[2*kb+1] = ffma2(w23[kb], xx0, sp0[2*kb+1]);
            sp1[2*kb]   = ffma2(w01[kb], xx1, sp1[2*kb]);
            sp1[2*kb+1] = ffma2(w23[kb], xx1, sp1[2*kb+1]);
        }

        // --- lazy tanh refresh: warp-uniform per 128-unit chunk (over-refresh safe) ---
        int S  = start_ge(i);
        int v2 = 32 + ((i + 1) >> 1);
        int E2 = start_ge(v2); if (E2 > 1024) E2 = 1024;
#pragma unroll
        for (int kb = 0; kb < 4; kb++) {
            int lo = half * 512 + kb * 128;
            if (lo < E2 && lo + 128 > S) {
                float a0, a1_, c0, c1;
                un2(sp0[2*kb], a0, a1_);   tp0[2*kb]   = mk2(tanh_mufu(a0), tanh_mufu(a1_));
                un2(sp0[2*kb+1], c0, c1);  tp0[2*kb+1] = mk2(tanh_mufu(c0), tanh_mufu(c1));
                un2(sp1[2*kb], a0, a1_);   tp1[2*kb]   = mk2(tanh_mufu(a0), tanh_mufu(a1_));
                un2(sp1[2*kb+1], c0, c1);  tp1[2*kb+1] = mk2(tanh_mufu(c0), tanh_mufu(c1));
            }
        }

        // rotate stage pointers
        unsigned t = sw0; sw0 = sw1; sw1 = sw2; sw2 = t;
    }

    // epilogue: half 0 stores (both halves computed identical x / log_det)
    if (half == 0) {
        if (!isfinite(xlo0)) xlo0 = 0.f;
        if (!isfinite(xhi0)) xhi0 = 0.f;
        if (!isfinite(xlo1)) xlo1 = 0.f;
        if (!isfinite(xhi1)) xhi1 = 0.f;
        out_x[r0 * 64 + 2 * l]     = xlo0;
        out_x[r0 * 64 + 2 * l + 1] = xhi0;
        out_x[r1 * 64 + 2 * l]     = xlo1;
        out_x[r1 * 64 + 2 * l + 1] = xhi1;
        if (l == 0) {
            if (!isfinite(ld0)) ld0 = 0.f;
            if (!isfinite(ld1)) ld1 = 0.f;
            out_ld[r0] = ld0;
            out_ld[r1] = ld1;
        }
    }
}

extern "C" void kernel_launch(void* const* d_in, const int* in_sizes, int n_in,
                              void* d_out, int out_size) {
    const float* z  = (const float*)d_in[0];   // (16384, 64)
    const float* W1 = (const float*)d_in[1];   // (1024, 64)
    const float* b1 = (const float*)d_in[2];   // (1024,)
    const float* W2 = (const float*)d_in[3];   // (128, 1024)
    const float* b2 = (const float*)d_in[4];   // (128,)
    float* out    = (float*)d_out;
    float* out_x  = out;                       // x: 16384*64 floats
    float* out_ld = out + B_ROWS * D_DIM;      // log_det: 16384 floats

    maf_prep<<<768, 256>>>(W1, b1, W2);
    maf_main<<<B_ROWS / 8, NTHREADS>>>(z, b2, out_x, out_ld);
}

// round 8
// speedup vs baseline: 4.4980x; 1.0330x over previous
#include <cuda_runtime.h>
#include <cuda_bf16.h>
#include <math.h>

// Shapes fixed by the problem: B=16384, D=64, H=1024, CLAMP=10.
#define B_ROWS 16384
#define D_DIM  64
#define H_DIM  1024
#define CLAMPV 10.0f
#define NTHREADS 256   // 8 warps = 2 groups; group = 4 warps = 4 rows

typedef unsigned long long ull;

// Packed weights, per step i (3072 floats each):
//   [0,1024)    : W1m column i   (masked, m0-sorted)
//   [1024,2048) : W2m row i      (mu row, masked)
//   [2048,3072) : W2m row 64+i   (alpha row, masked)
__device__ __align__(16) float g_w[64 * 3072];
__device__ __align__(16) float g_b1p[H_DIM];

// m0[h] = h % 63 (values 0..62), H sorted stably by m0.
__host__ __device__ __forceinline__ int start_ge(int v) {
    return (v <= 16) ? 17 * v : 16 * v + 16;
}

__device__ __forceinline__ float tanh_mufu(float x) {
    float y; asm("tanh.approx.f32 %0, %1;" : "=f"(y) : "f"(x)); return y;
}
__device__ __forceinline__ ull ffma2(ull a, ull b, ull c) {
    ull d;
    asm("fma.rn.f32x2 %0, %1, %2, %3;" : "=l"(d) : "l"(a), "l"(b), "l"(c));
    return d;
}
__device__ __forceinline__ ull mk2(float lo, float hi) {
    ull r; asm("mov.b64 %0, {%1, %2};" : "=l"(r) : "f"(lo), "f"(hi)); return r;
}
__device__ __forceinline__ void un2(ull u, float& lo, float& hi) {
    asm("mov.b64 {%0, %1}, %2;" : "=f"(lo), "=f"(hi) : "l"(u));
}
__device__ __forceinline__ void lds2(ull& a, ull& b, unsigned addr) {
    asm volatile("ld.shared.v2.u64 {%0, %1}, [%2];" : "=l"(a), "=l"(b) : "r"(addr));
}
__device__ __forceinline__ void cp16(unsigned smem_dst, const void* gsrc) {
    asm volatile("cp.async.cg.shared.global [%0], [%1], 16;" :: "r"(smem_dst), "l"(gsrc));
}
__device__ __forceinline__ void cp_commit() {
    asm volatile("cp.async.commit_group;" ::: "memory");
}
__device__ __forceinline__ void cp_wait1() {
    asm volatile("cp.async.wait_group 1;" ::: "memory");
}

// ---------------- prep: permute + mask + pack weights ----------------
__global__ void maf_prep(const float* __restrict__ W1,
                         const float* __restrict__ b1,
                         const float* __restrict__ W2) {
    int gid = blockIdx.x * blockDim.x + threadIdx.x;
    if (gid >= 64 * 3072) return;
    int i   = gid / 3072;
    int rem = gid - i * 3072;
    int sec = rem >> 10;
    int p   = rem & 1023;
    int v, k2;
    if (p < 272) { v = p / 17; k2 = p - v * 17; }
    else         { int r = p - 272; v = 16 + (r >> 4); k2 = r & 15; }
    int h = v + 63 * k2;

    float val;
    if (sec == 0)      val = (i <= v)            ? W1[h * 64 + i]          : 0.0f;
    else if (sec == 1) val = (v < (i >> 1))      ? W2[i * 1024 + h]        : 0.0f;
    else               val = (v < 32 + (i >> 1)) ? W2[(64 + i) * 1024 + h] : 0.0f;
    g_w[gid] = val;

    if (gid < 1024) {
        int pp = gid;
        int vv, kk;
        if (pp < 272) { vv = pp / 17; kk = pp - vv * 17; }
        else          { int r = pp - 272; vv = 16 + (r >> 4); kk = r & 15; }
        g_b1p[gid] = b1[vv + 63 * kk];
    }
}

// --------- main: group of 4 warps = 4 rows; warp owns 256 units ---------
// Quarter q covers sorted positions [q*256, (q+1)*256), lane l: 8 units
// (2 chunks of 4). Reduction: 8 partials (4 rows x mu/alpha) via
// role-rotation; class c = l&7 (c&3 = row, c&4 = alpha). Distributed tail.
__global__ void __launch_bounds__(NTHREADS, 2) maf_main(
    const float* __restrict__ z, const float* __restrict__ b2,
    float* __restrict__ out_x, float* __restrict__ out_ld)
{
    __shared__ __align__(16) float sw[3][3072];
    __shared__ __align__(16) float sred[2][2][8][4]; // [parity][group][class][quarter]
    __shared__ float zs[2][4][65];                   // padded rows: no bank conflicts
    __shared__ float b2s[128];

    const int tid = threadIdx.x;
    const int l   = tid & 31;
    const int q   = (tid >> 5) & 3;
    const int grp = tid >> 7;
    const int g   = blockIdx.x * 2 + grp;            // group id: rows 4g..4g+3

    // stage z (8 rows) and b2 into smem
    for (int j = tid; j < 512; j += NTHREADS) {
        int gg = j >> 8, r = (j >> 6) & 3, i = j & 63;
        zs[gg][r][i] = z[(blockIdx.x * 8 + gg * 4 + r) * 64 + i];
    }
    if (tid < 128) b2s[tid] = b2[tid];

    // rotating stage base addresses
    unsigned swA = (unsigned)__cvta_generic_to_shared(&sw[0][0]);
    unsigned sw0 = swA, sw1 = swA + 12288, sw2 = swA + 24576;

    // prologue: prefetch steps 0 and 1
    {
        const float* s0 = g_w + tid * 4;
        cp16(sw0 + tid * 16,        s0);
        cp16(sw0 + tid * 16 + 4096, s0 + 1024);
        cp16(sw0 + tid * 16 + 8192, s0 + 2048);
        cp_commit();
        const float* s1 = g_w + 3072 + tid * 4;
        cp16(sw1 + tid * 16,        s1);
        cp16(sw1 + tid * 16 + 4096, s1 + 1024);
        cp16(sw1 + tid * 16 + 8192, s1 + 2048);
        cp_commit();
    }
    const float* srcp = g_w + 2 * 3072 + tid * 4;

    const unsigned laneoff = (unsigned)(q * 1024 + l * 16);

    // state: 4 rows x (4 ull s + 4 ull t)
    ull sp[4][4], tp[4][4];
    const float4* b1v = (const float4*)(g_b1p);
#pragma unroll
    for (int kb = 0; kb < 2; kb++) {
        float4 b = b1v[q * 64 + kb * 32 + l];
        ull p01 = mk2(b.x, b.y), p23 = mk2(b.z, b.w);
        ull t01 = mk2(tanh_mufu(b.x), tanh_mufu(b.y));
        ull t23 = mk2(tanh_mufu(b.z), tanh_mufu(b.w));
#pragma unroll
        for (int r = 0; r < 4; r++) {
            sp[r][2*kb] = p01; sp[r][2*kb+1] = p23;
            tp[r][2*kb] = t01; tp[r][2*kb+1] = t23;
        }
    }

    float xlo[4] = {0,0,0,0}, xhi[4] = {0,0,0,0};
    float ld = 0.f;
    const bool isA = (l & 4);

    cp_wait1();          // stage 0 resident
    __syncthreads();     // publish stage 0 + z/b2 staging

#pragma unroll 1
    for (int i = 0; i < 64; i++) {
        const unsigned swb = sw0 + laneoff;

        // W1 quarter (held in regs across barrier for the update)
        ull w01[2], w23[2];
#pragma unroll
        for (int kb = 0; kb < 2; kb++) lds2(w01[kb], w23[kb], swb + kb * 512);

        // dots: 8 chains (4 rows x mu/alpha)
        ull acc[8];
#pragma unroll
        for (int c = 0; c < 8; c++) acc[c] = 0ull;
#pragma unroll
        for (int kb = 0; kb < 2; kb++) {
            ull wm01, wm23, wa01, wa23;
            lds2(wm01, wm23, swb + 4096 + kb * 512);
            lds2(wa01, wa23, swb + 8192 + kb * 512);
#pragma unroll
            for (int r = 0; r < 4; r++) {
                acc[r]     = ffma2(tp[r][2*kb],   wm01, acc[r]);
                acc[r]     = ffma2(tp[r][2*kb+1], wm23, acc[r]);
                acc[4 + r] = ffma2(tp[r][2*kb],   wa01, acc[4 + r]);
                acc[4 + r] = ffma2(tp[r][2*kb+1], wa23, acc[4 + r]);
            }
        }
        float v[8];
#pragma unroll
        for (int c = 0; c < 8; c++) { float u, w; un2(acc[c], u, w); v[c] = u + w; }

        // role-rotation reduction: 9 SHFL for 8 values; lane ends with class l&7
        float f;
        {
            bool b0 = l & 1;
            float s0_ = b0 ? v[0] : v[1], k0 = b0 ? v[1] : v[0];
            k0 += __shfl_xor_sync(0xffffffffu, s0_, 1);
            float s1_ = b0 ? v[2] : v[3], k1 = b0 ? v[3] : v[2];
            k1 += __shfl_xor_sync(0xffffffffu, s1_, 1);
            float s2_ = b0 ? v[4] : v[5], k2 = b0 ? v[5] : v[4];
            k2 += __shfl_xor_sync(0xffffffffu, s2_, 1);
            float s3_ = b0 ? v[6] : v[7], k3 = b0 ? v[7] : v[6];
            k3 += __shfl_xor_sync(0xffffffffu, s3_, 1);
            bool b1_ = l & 2;
            float sm = b1_ ? k0 : k1, km = b1_ ? k1 : k0;
            km += __shfl_xor_sync(0xffffffffu, sm, 2);
            float sa = b1_ ? k2 : k3, ka = b1_ ? k3 : k2;
            ka += __shfl_xor_sync(0xffffffffu, sa, 2);
            bool b2_ = l & 4;
            float sf = b2_ ? km : ka, kf = b2_ ? ka : km;
            kf += __shfl_xor_sync(0xffffffffu, sf, 4);
            kf += __shfl_xor_sync(0xffffffffu, kf, 8);
            kf += __shfl_xor_sync(0xffffffffu, kf, 16);
            f = kf;
        }
        if (l < 8) sred[i & 1][grp][l][q] = f;

        // prefetch stage i+2
        if (i + 2 < 64) {
            cp16(sw2 + tid * 16,        srcp);
            cp16(sw2 + tid * 16 + 4096, srcp + 1024);
            cp16(sw2 + tid * 16 + 8192, srcp + 2048);
            srcp += 3072;
        }
        cp_commit();
        cp_wait1();          // stage i+1 resident
        __syncthreads();     // publish stage i+1 + sred exchange

        // combine quarters for my class, add b2, exchange mu<->alpha
        float4 cf = *(const float4*)&sred[i & 1][grp][l & 7][0];
        float cv = (cf.x + cf.y) + (cf.z + cf.w);
        cv += b2s[(isA ? 64 : 0) + i];
        float pv = __shfl_xor_sync(0xffffffffu, cv, 4);
        float mu = isA ? pv : cv;
        float al = isA ? cv : pv;
        mu = fminf(fmaxf(mu, -CLAMPV), CLAMPV);
        al = fminf(fmaxf(al, -CLAMPV), CLAMPV);
        float zv = zs[grp][l & 3][i];
        float x  = fmaf(zv, __expf(al), mu);
        ld += al;                                  // meaningful in alpha lanes

        float x0 = __shfl_sync(0xffffffffu, x, 0);
        float x1 = __shfl_sync(0xffffffffu, x, 1);
        float x2 = __shfl_sync(0xffffffffu, x, 2);
        float x3 = __shfl_sync(0xffffffffu, x, 3);
        if ((i >> 1) == l) {
            if (i & 1) { xhi[0] = x0; xhi[1] = x1; xhi[2] = x2; xhi[3] = x3; }
            else       { xlo[0] = x0; xlo[1] = x1; xlo[2] = x2; xlo[3] = x3; }
        }

        // rank-1 update (register-held W1; zeros mask the suffix)
        ull xx[4] = { mk2(x0, x0), mk2(x1, x1), mk2(x2, x2), mk2(x3, x3) };
#pragma unroll
        for (int kb = 0; kb < 2; kb++) {
#pragma unroll
            for (int r = 0; r < 4; r++) {
                sp[r][2*kb]   = ffma2(w01[kb], xx[r], sp[r][2*kb]);
                sp[r][2*kb+1] = ffma2(w23[kb], xx[r], sp[r][2*kb+1]);
            }
        }

        // lazy tanh refresh: warp-uniform per 128-unit chunk (over-refresh safe)
        int S  = start_ge(i);
        int v2 = 32 + ((i + 1) >> 1);
        int E2 = start_ge(v2); if (E2 > 1024) E2 = 1024;
#pragma unroll
        for (int kb = 0; kb < 2; kb++) {
            int lo = q * 256 + kb * 128;
            if (lo < E2 && lo + 128 > S) {
#pragma unroll
                for (int r = 0; r < 4; r++) {
                    float a0, a1_, c0, c1;
                    un2(sp[r][2*kb], a0, a1_);
                    tp[r][2*kb]   = mk2(tanh_mufu(a0), tanh_mufu(a1_));
                    un2(sp[r][2*kb+1], c0, c1);
                    tp[r][2*kb+1] = mk2(tanh_mufu(c0), tanh_mufu(c1));
                }
            }
        }

        // rotate stage pointers
        unsigned t = sw0; sw0 = sw1; sw1 = sw2; sw2 = t;
    }

    // epilogue: quarter 0 stores (all quarters hold identical x / ld classes)
    if (q == 0) {
        int base = g * 4;
#pragma unroll
        for (int r = 0; r < 4; r++) {
            float a = xlo[r], b = xhi[r];
            if (!isfinite(a)) a = 0.f;
            if (!isfinite(b)) b = 0.f;
            *(float2*)(out_x + (base + r) * 64 + 2 * l) = make_float2(a, b);
        }
        if (l >= 4 && l < 8) {
            float L = ld;
            if (!isfinite(L)) L = 0.f;
            out_ld[base + (l - 4)] = L;
        }
    }
}

extern "C" void kernel_launch(void* const* d_in, const int* in_sizes, int n_in,
                              void* d_out, int out_size) {
    const float* z  = (const float*)d_in[0];   // (16384, 64)
    const float* W1 = (const float*)d_in[1];   // (1024, 64)
    const float* b1 = (const float*)d_in[2];   // (1024,)
    const float* W2 = (const float*)d_in[3];   // (128, 1024)
    const float* b2 = (const float*)d_in[4];   // (128,)
    float* out    = (float*)d_out;
    float* out_x  = out;                       // x: 16384*64 floats
    float* out_ld = out + B_ROWS * D_DIM;      // log_det: 16384 floats

    maf_prep<<<768, 256>>>(W1, b1, W2);
    maf_main<<<B_ROWS / 8, NTHREADS>>>(z, b2, out_x, out_ld);  // 8 rows/block
}

// round 9
// speedup vs baseline: 4.8070x; 1.0687x over previous
#include <cuda_runtime.h>
#include <cuda_bf16.h>
#include <math.h>

// Shapes fixed by the problem: B=16384, D=64, H=1024, CLAMP=10.
#define B_ROWS 16384
#define D_DIM  64
#define H_DIM  1024
#define CLAMPV 10.0f
#define NTHREADS 128   // 1 group of 4 warps = 4 rows per block; 4 blocks/SM

typedef unsigned long long ull;

// Packed weights, per step i (3072 floats each):
//   [0,1024)    : W1m column i   (masked, m0-sorted)
//   [1024,2048) : W2m row i      (mu row, masked)
//   [2048,3072) : W2m row 64+i   (alpha row, masked)
__device__ __align__(16) float g_w[64 * 3072];
__device__ __align__(16) float g_b1p[H_DIM];

// m0[h] = h % 63 (values 0..62), H sorted stably by m0.
__host__ __device__ __forceinline__ int start_ge(int v) {
    return (v <= 16) ? 17 * v : 16 * v + 16;
}

__device__ __forceinline__ float tanh_mufu(float x) {
    float y; asm("tanh.approx.f32 %0, %1;" : "=f"(y) : "f"(x)); return y;
}
__device__ __forceinline__ ull ffma2(ull a, ull b, ull c) {
    ull d;
    asm("fma.rn.f32x2 %0, %1, %2, %3;" : "=l"(d) : "l"(a), "l"(b), "l"(c));
    return d;
}
__device__ __forceinline__ ull mk2(float lo, float hi) {
    ull r; asm("mov.b64 %0, {%1, %2};" : "=l"(r) : "f"(lo), "f"(hi)); return r;
}
__device__ __forceinline__ void un2(ull u, float& lo, float& hi) {
    asm("mov.b64 {%0, %1}, %2;" : "=f"(lo), "=f"(hi) : "l"(u));
}
__device__ __forceinline__ void lds2(ull& a, ull& b, unsigned addr) {
    asm volatile("ld.shared.v2.u64 {%0, %1}, [%2];" : "=l"(a), "=l"(b) : "r"(addr));
}
__device__ __forceinline__ void cp16(unsigned smem_dst, const void* gsrc) {
    asm volatile("cp.async.cg.shared.global [%0], [%1], 16;" :: "r"(smem_dst), "l"(gsrc));
}
__device__ __forceinline__ void cp_commit() {
    asm volatile("cp.async.commit_group;" ::: "memory");
}
__device__ __forceinline__ void cp_wait1() {
    asm volatile("cp.async.wait_group 1;" ::: "memory");
}

// ---------------- prep: permute + mask + pack weights ----------------
__global__ void maf_prep(const float* __restrict__ W1,
                         const float* __restrict__ b1,
                         const float* __restrict__ W2) {
    int gid = blockIdx.x * blockDim.x + threadIdx.x;
    if (gid >= 64 * 3072) return;
    int i   = gid / 3072;
    int rem = gid - i * 3072;
    int sec = rem >> 10;
    int p   = rem & 1023;
    int v, k2;
    if (p < 272) { v = p / 17; k2 = p - v * 17; }
    else         { int r = p - 272; v = 16 + (r >> 4); k2 = r & 15; }
    int h = v + 63 * k2;

    float val;
    if (sec == 0)      val = (i <= v)            ? W1[h * 64 + i]          : 0.0f;
    else if (sec == 1) val = (v < (i >> 1))      ? W2[i * 1024 + h]        : 0.0f;
    else               val = (v < 32 + (i >> 1)) ? W2[(64 + i) * 1024 + h] : 0.0f;
    g_w[gid] = val;

    if (gid < 1024) {
        int pp = gid;
        int vv, kk;
        if (pp < 272) { vv = pp / 17; kk = pp - vv * 17; }
        else          { int r = pp - 272; vv = 16 + (r >> 4); kk = r & 15; }
        g_b1p[gid] = b1[vv + 63 * kk];
    }
}

// --------- main: one group of 4 warps = 4 rows; 4 blocks/SM ---------
// Warp q owns INTERLEAVED 128-unit chunks {q, q+4} (balances the moving
// tanh-refresh window across warps). Lane l: 8 units (4 per chunk).
// Reduction: 8 partials (4 rows x mu/alpha) via role-rotation; class
// c = l&7 (c&3 = row, c&4 = alpha). Distributed scalar tail.
__global__ void __launch_bounds__(NTHREADS, 4) maf_main(
    const float* __restrict__ z, const float* __restrict__ b2,
    float* __restrict__ out_x, float* __restrict__ out_ld)
{
    __shared__ __align__(16) float sw[3][3072];
    __shared__ __align__(16) float sred[2][8][4];  // [parity][class][quarter]
    __shared__ float zs[4][65];                    // padded rows
    __shared__ float b2s[128];

    const int tid = threadIdx.x;
    const int l   = tid & 31;
    const int q   = tid >> 5;                      // warp 0..3

    // stage z (4 rows) and b2 into smem
    for (int j = tid; j < 256; j += NTHREADS) {
        int r = j >> 6, c = j & 63;
        zs[r][c] = z[(blockIdx.x * 4 + r) * 64 + c];
    }
    b2s[tid] = b2[tid];

    // rotating stage base addresses
    unsigned swA = (unsigned)__cvta_generic_to_shared(&sw[0][0]);
    unsigned sw0 = swA, sw1 = swA + 12288, sw2 = swA + 24576;

    // prologue: prefetch steps 0 and 1 (6 x 16B per thread per step)
    {
        const float* s0 = g_w + tid * 4;
#pragma unroll
        for (int k = 0; k < 6; k++) cp16(sw0 + tid * 16 + k * 2048, s0 + k * 512);
        cp_commit();
        const float* s1 = g_w + 3072 + tid * 4;
#pragma unroll
        for (int k = 0; k < 6; k++) cp16(sw1 + tid * 16 + k * 2048, s1 + k * 512);
        cp_commit();
    }
    const float* srcp = g_w + 2 * 3072 + tid * 4;

    const unsigned laneoff = (unsigned)(q * 512 + l * 16);

    // state: 4 rows x (chunk j: s[2j],s[2j+1], t likewise), chunk j = q+4j
    ull sp[4][4], tp[4][4];
    const float4* b1v = (const float4*)(g_b1p);
#pragma unroll
    for (int j = 0; j < 2; j++) {
        float4 b = b1v[(q + 4 * j) * 32 + l];
        ull p01 = mk2(b.x, b.y), p23 = mk2(b.z, b.w);
        ull t01 = mk2(tanh_mufu(b.x), tanh_mufu(b.y));
        ull t23 = mk2(tanh_mufu(b.z), tanh_mufu(b.w));
#pragma unroll
        for (int r = 0; r < 4; r++) {
            sp[r][2*j] = p01; sp[r][2*j+1] = p23;
            tp[r][2*j] = t01; tp[r][2*j+1] = t23;
        }
    }

    float xlo[4] = {0,0,0,0}, xhi[4] = {0,0,0,0};
    float ld = 0.f;
    const bool isA = (l & 4);

    cp_wait1();          // stage 0 resident
    __syncthreads();     // publish stage 0 + z/b2 staging

#pragma unroll 1
    for (int i = 0; i < 64; i++) {
        const unsigned swb = sw0 + laneoff;
        const int S   = start_ge(i);
        const int Pmu = start_ge(i >> 1);
        const int Pal = start_ge(32 + (i >> 1));

        // W1 chunks (held in regs across barrier); skip all-zero chunks
        ull w01[2], w23[2];
        bool w1a[2];
#pragma unroll
        for (int j = 0; j < 2; j++) {
            int c = q + 4 * j;
            w1a[j] = (c * 128 + 128 > S);
            if (w1a[j]) lds2(w01[j], w23[j], swb + j * 2048);
        }

        // dots: 8 chains (4 rows x mu/alpha); skip all-zero chunks
        ull acc[8];
#pragma unroll
        for (int c = 0; c < 8; c++) acc[c] = 0ull;
#pragma unroll
        for (int j = 0; j < 2; j++) {
            int c = q + 4 * j;
            if (c * 128 < Pmu) {
                ull wm01, wm23;
                lds2(wm01, wm23, swb + 4096 + j * 2048);
#pragma unroll
                for (int r = 0; r < 4; r++) {
                    acc[r] = ffma2(tp[r][2*j],   wm01, acc[r]);
                    acc[r] = ffma2(tp[r][2*j+1], wm23, acc[r]);
                }
            }
            if (c * 128 < Pal) {
                ull wa01, wa23;
                lds2(wa01, wa23, swb + 8192 + j * 2048);
#pragma unroll
                for (int r = 0; r < 4; r++) {
                    acc[4 + r] = ffma2(tp[r][2*j],   wa01, acc[4 + r]);
                    acc[4 + r] = ffma2(tp[r][2*j+1], wa23, acc[4 + r]);
                }
            }
        }
        float v[8];
#pragma unroll
        for (int c = 0; c < 8; c++) { float u, w; un2(acc[c], u, w); v[c] = u + w; }

        // role-rotation reduction: 9 SHFL for 8 values; lane ends with class l&7
        float f;
        {
            bool b0 = l & 1;
            float s0_ = b0 ? v[0] : v[1], k0 = b0 ? v[1] : v[0];
            k0 += __shfl_xor_sync(0xffffffffu, s0_, 1);
            float s1_ = b0 ? v[2] : v[3], k1 = b0 ? v[3] : v[2];
            k1 += __shfl_xor_sync(0xffffffffu, s1_, 1);
            float s2_ = b0 ? v[4] : v[5], k2 = b0 ? v[5] : v[4];
            k2 += __shfl_xor_sync(0xffffffffu, s2_, 1);
            float s3_ = b0 ? v[6] : v[7], k3 = b0 ? v[7] : v[6];
            k3 += __shfl_xor_sync(0xffffffffu, s3_, 1);
            bool b1_ = l & 2;
            float sm = b1_ ? k0 : k1, km = b1_ ? k1 : k0;
            km += __shfl_xor_sync(0xffffffffu, sm, 2);
            float sa = b1_ ? k2 : k3, ka = b1_ ? k3 : k2;
            ka += __shfl_xor_sync(0xffffffffu, sa, 2);
            bool b2_ = l & 4;
            float sf = b2_ ? km : ka, kf = b2_ ? ka : km;
            kf += __shfl_xor_sync(0xffffffffu, sf, 4);
            kf += __shfl_xor_sync(0xffffffffu, kf, 8);
            kf += __shfl_xor_sync(0xffffffffu, kf, 16);
            f = kf;
        }
        if (l < 8) sred[i & 1][l][q] = f;

        // prefetch stage i+2
        if (i + 2 < 64) {
#pragma unroll
            for (int k = 0; k < 6; k++) cp16(sw2 + tid * 16 + k * 2048, srcp + k * 512);
            srcp += 3072;
        }
        cp_commit();
        cp_wait1();          // stage i+1 resident
        __syncthreads();     // publish stage i+1 + sred exchange (4 warps only)

        // combine quarters for my class, add b2, exchange mu<->alpha
        float4 cf = *(const float4*)&sred[i & 1][l & 7][0];
        float cv = (cf.x + cf.y) + (cf.z + cf.w);
        cv += b2s[(isA ? 64 : 0) + i];
        float pv = __shfl_xor_sync(0xffffffffu, cv, 4);
        float mu = isA ? pv : cv;
        float al = isA ? cv : pv;
        mu = fminf(fmaxf(mu, -CLAMPV), CLAMPV);
        al = fminf(fmaxf(al, -CLAMPV), CLAMPV);
        float zv = zs[l & 3][i];
        float x  = fmaf(zv, __expf(al), mu);
        ld += al;                                  // meaningful in alpha lanes

        float x0 = __shfl_sync(0xffffffffu, x, 0);
        float x1 = __shfl_sync(0xffffffffu, x, 1);
        float x2 = __shfl_sync(0xffffffffu, x, 2);
        float x3 = __shfl_sync(0xffffffffu, x, 3);
        if ((i >> 1) == l) {
            if (i & 1) { xhi[0] = x0; xhi[1] = x1; xhi[2] = x2; xhi[3] = x3; }
            else       { xlo[0] = x0; xlo[1] = x1; xlo[2] = x2; xlo[3] = x3; }
        }

        // rank-1 update (register-held W1; skip all-zero chunks)
        ull xx[4] = { mk2(x0, x0), mk2(x1, x1), mk2(x2, x2), mk2(x3, x3) };
#pragma unroll
        for (int j = 0; j < 2; j++) {
            if (w1a[j]) {
#pragma unroll
                for (int r = 0; r < 4; r++) {
                    sp[r][2*j]   = ffma2(w01[j], xx[r], sp[r][2*j]);
                    sp[r][2*j+1] = ffma2(w23[j], xx[r], sp[r][2*j+1]);
                }
            }
        }

        // lazy tanh refresh on [S, E2) = [start_ge(i), start_ge(32+(i+1)/2))
        if (i < 63) {
            int v2 = 32 + ((i + 1) >> 1);
            int E2 = start_ge(v2); if (E2 > 1024) E2 = 1024;
#pragma unroll
            for (int j = 0; j < 2; j++) {
                int lo = (q + 4 * j) * 128;
                if (lo < E2 && lo + 128 > S) {
#pragma unroll
                    for (int r = 0; r < 4; r++) {
                        float a0, a1_, c0, c1;
                        un2(sp[r][2*j], a0, a1_);
                        tp[r][2*j]   = mk2(tanh_mufu(a0), tanh_mufu(a1_));
                        un2(sp[r][2*j+1], c0, c1);
                        tp[r][2*j+1] = mk2(tanh_mufu(c0), tanh_mufu(c1));
                    }
                }
            }
        }

        // rotate stage pointers
        unsigned t = sw0; sw0 = sw1; sw1 = sw2; sw2 = t;
    }

    // epilogue: warp 0 stores (all warps hold identical x / ld classes)
    if (q == 0) {
        int base = blockIdx.x * 4;
#pragma unroll
        for (int r = 0; r < 4; r++) {
            float a = xlo[r], b = xhi[r];
            if (!isfinite(a)) a = 0.f;
            if (!isfinite(b)) b = 0.f;
            *(float2*)(out_x + (base + r) * 64 + 2 * l) = make_float2(a, b);
        }
        if (l >= 4 && l < 8) {
            float L = ld;
            if (!isfinite(L)) L = 0.f;
            out_ld[base + (l - 4)] = L;
        }
    }
}

extern "C" void kernel_launch(void* const* d_in, const int* in_sizes, int n_in,
                              void* d_out, int out_size) {
    const float* z  = (const float*)d_in[0];   // (16384, 64)
    const float* W1 = (const float*)d_in[1];   // (1024, 64)
    const float* b1 = (const float*)d_in[2];   // (1024,)
    const float* W2 = (const float*)d_in[3];   // (128, 1024)
    const float* b2 = (const float*)d_in[4];   // (128,)
    float* out    = (float*)d_out;
    float* out_x  = out;                       // x: 16384*64 floats
    float* out_ld = out + B_ROWS * D_DIM;      // log_det: 16384 floats

    // hint: maximize smem carveout so 4 blocks (4 x ~38.7KB) fit per SM
    static int carveout_set = 0;
    if (!carveout_set) {
        cudaFuncSetAttribute(maf_main, cudaFuncAttributePreferredSharedMemoryCarveout, 100);
        carveout_set = 1;
    }

    maf_prep<<<768, 256>>>(W1, b1, W2);
    maf_main<<<B_ROWS / 4, NTHREADS>>>(z, b2, out_x, out_ld);  // 4 rows/block
}

// round 10
// speedup vs baseline: 5.3750x; 1.1182x over previous
#include <cuda_runtime.h>
#include <cuda_bf16.h>
#include <math.h>

// Shapes fixed by the problem: B=16384, D=64, H=1024, CLAMP=10.
#define B_ROWS 16384
#define D_DIM  64
#define H_DIM  1024
#define CLAMPV 10.0f
#define NTHREADS 128   // 4 warps = 4 rows per block; 4 blocks/SM

typedef unsigned long long ull;

// Packed weights, per step i (3072 floats each):
//   [0,1024)    : W1m column i   (masked, m0-sorted)
//   [1024,2048) : W2m row i      (mu row, masked)
//   [2048,3072) : W2m row 64+i   (alpha row, masked)
__device__ __align__(16) float g_w[64 * 3072];
__device__ __align__(16) float g_b1p[H_DIM];
// Per-step chunk-activity masks (8 chunks of 128 units):
//   bits [0:8)  W1 chunk nonzero   (c*128+128 > S_i)
//   bits [8:12) mu chunk nonzero   (c*128 < Pmu_i), c<4 (Pmu <= 512 always)
//   bits [12:20) alpha chunk nonzero (c*128 < Pal_i)
//   bits [20:28) tanh-refresh chunk  (overlaps [S_i, E2_i), i<63)
__device__ unsigned g_masks[64];

// m0[h] = h % 63 (values 0..62), H sorted stably by m0.
__host__ __device__ __forceinline__ int start_ge(int v) {
    return (v <= 16) ? 17 * v : 16 * v + 16;
}

__device__ __forceinline__ float tanh_mufu(float x) {
    float y; asm("tanh.approx.f32 %0, %1;" : "=f"(y) : "f"(x)); return y;
}
__device__ __forceinline__ ull ffma2(ull a, ull b, ull c) {
    ull d;
    asm("fma.rn.f32x2 %0, %1, %2, %3;" : "=l"(d) : "l"(a), "l"(b), "l"(c));
    return d;
}
__device__ __forceinline__ ull mk2(float lo, float hi) {
    ull r; asm("mov.b64 %0, {%1, %2};" : "=l"(r) : "f"(lo), "f"(hi)); return r;
}
__device__ __forceinline__ void un2(ull u, float& lo, float& hi) {
    asm("mov.b64 {%0, %1}, %2;" : "=f"(lo), "=f"(hi) : "l"(u));
}
__device__ __forceinline__ void lds2(ull& a, ull& b, unsigned addr) {
    asm volatile("ld.shared.v2.u64 {%0, %1}, [%2];" : "=l"(a), "=l"(b) : "r"(addr));
}
__device__ __forceinline__ void cp16(unsigned smem_dst, const void* gsrc) {
    asm volatile("cp.async.cg.shared.global [%0], [%1], 16;" :: "r"(smem_dst), "l"(gsrc));
}
__device__ __forceinline__ void cp_commit() {
    asm volatile("cp.async.commit_group;" ::: "memory");
}
__device__ __forceinline__ void cp_wait1() {
    asm volatile("cp.async.wait_group 1;" ::: "memory");
}

// ---------------- prep: permute + mask + pack weights + masks ----------------
__global__ void maf_prep(const float* __restrict__ W1,
                         const float* __restrict__ b1,
                         const float* __restrict__ W2) {
    int gid = blockIdx.x * blockDim.x + threadIdx.x;
    if (gid >= 64 * 3072) return;
    int i   = gid / 3072;
    int rem = gid - i * 3072;
    int sec = rem >> 10;
    int p   = rem & 1023;
    int v, k2;
    if (p < 272) { v = p / 17; k2 = p - v * 17; }
    else         { int r = p - 272; v = 16 + (r >> 4); k2 = r & 15; }
    int h = v + 63 * k2;

    float val;
    if (sec == 0)      val = (i <= v)            ? W1[h * 64 + i]          : 0.0f;
    else if (sec == 1) val = (v < (i >> 1))      ? W2[i * 1024 + h]        : 0.0f;
    else               val = (v < 32 + (i >> 1)) ? W2[(64 + i) * 1024 + h] : 0.0f;
    g_w[gid] = val;

    if (gid < 1024) {
        int pp = gid;
        int vv, kk;
        if (pp < 272) { vv = pp / 17; kk = pp - vv * 17; }
        else          { int r = pp - 272; vv = 16 + (r >> 4); kk = r & 15; }
        g_b1p[gid] = b1[vv + 63 * kk];
    }

    if (gid < 64) {
        int st = gid;
        int S   = start_ge(st);
        int Pmu = start_ge(st >> 1);
        int Pal = start_ge(32 + (st >> 1)); if (Pal > 1024) Pal = 1024;
        int v2  = 32 + ((st + 1) >> 1);
        int E2  = start_ge(v2); if (E2 > 1024) E2 = 1024;
        unsigned m = 0;
        for (int c = 0; c < 8; c++) {
            if (c * 128 + 128 > S)              m |= 1u << c;
            if (c < 4 && c * 128 < Pmu)         m |= 1u << (8 + c);
            if (c * 128 < Pal)                  m |= 1u << (12 + c);
            if (st < 63 && c * 128 < E2 && c * 128 + 128 > S)
                                                m |= 1u << (20 + c);
        }
        g_masks[st] = m;
    }
}

// --------- main: 4 warps = 4 rows; warp q owns chunks {q, q+4} ---------
__global__ void __launch_bounds__(NTHREADS, 4) maf_main(
    const float* __restrict__ z, const float* __restrict__ b2,
    float* __restrict__ out_x, float* __restrict__ out_ld)
{
    __shared__ __align__(16) float sw[3][3072];
    __shared__ __align__(16) float sred[2][8][4];  // [parity][class][quarter]
    __shared__ float zs[4][65];
    __shared__ float sx[4][65];                    // per-step x, written by warp 0
    __shared__ float b2s[128];
    __shared__ unsigned smask[64];

    const int tid = threadIdx.x;
    const int l   = tid & 31;
    const int q   = tid >> 5;                      // warp 0..3

    // stage z, b2, masks into smem
    for (int j = tid; j < 256; j += NTHREADS) {
        int r = j >> 6, c = j & 63;
        zs[r][c] = z[(blockIdx.x * 4 + r) * 64 + c];
    }
    b2s[tid] = b2[tid];
    if (tid < 64) smask[tid] = g_masks[tid];

    // rotating stage base addresses
    unsigned swA = (unsigned)__cvta_generic_to_shared(&sw[0][0]);
    unsigned sw0 = swA, sw1 = swA + 12288, sw2 = swA + 24576;

    // prologue: prefetch steps 0 and 1 (unconditional full copies)
    {
        const float* s0 = g_w + tid * 4;
#pragma unroll
        for (int k = 0; k < 6; k++) cp16(sw0 + tid * 16 + k * 2048, s0 + k * 512);
        cp_commit();
        const float* s1 = g_w + 3072 + tid * 4;
#pragma unroll
        for (int k = 0; k < 6; k++) cp16(sw1 + tid * 16 + k * 2048, s1 + k * 512);
        cp_commit();
    }
    const float* srcp = g_w + 2 * 3072 + tid * 4;

    const unsigned laneoff = (unsigned)(q * 512 + l * 16);

    // state: 4 rows x (chunk j: s[2j],s[2j+1], t likewise), chunk j -> q+4j
    ull sp[4][4], tp[4][4];
    const float4* b1v = (const float4*)(g_b1p);
#pragma unroll
    for (int j = 0; j < 2; j++) {
        float4 b = b1v[(q + 4 * j) * 32 + l];
        ull p01 = mk2(b.x, b.y), p23 = mk2(b.z, b.w);
        ull t01 = mk2(tanh_mufu(b.x), tanh_mufu(b.y));
        ull t23 = mk2(tanh_mufu(b.z), tanh_mufu(b.w));
#pragma unroll
        for (int r = 0; r < 4; r++) {
            sp[r][2*j] = p01; sp[r][2*j+1] = p23;
            tp[r][2*j] = t01; tp[r][2*j+1] = t23;
        }
    }

    float ld = 0.f;
    const bool isA = (l & 4);

    cp_wait1();          // stage 0 resident
    __syncthreads();     // publish stage 0 + staging

#pragma unroll 1
    for (int i = 0; i < 64; i++) {
        const unsigned swb = sw0 + laneoff;
        const unsigned mC = smask[i];

        // W1 chunks (held in regs across barrier); skip all-zero chunks
        ull w01[2], w23[2];
        bool w1a0 = (mC >> q) & 1, w1a1 = (mC >> (q + 4)) & 1;
        if (w1a0) lds2(w01[0], w23[0], swb);
        if (w1a1) lds2(w01[1], w23[1], swb + 2048);

        // dots: 8 chains (4 rows x mu/alpha); mask-gated chunks
        ull acc[8];
#pragma unroll
        for (int c = 0; c < 8; c++) acc[c] = 0ull;
        if ((mC >> (8 + q)) & 1) {                 // mu: only chunk j=0 can be live
            ull wm01, wm23;
            lds2(wm01, wm23, swb + 4096);
#pragma unroll
            for (int r = 0; r < 4; r++) {
                acc[r] = ffma2(tp[r][0], wm01, acc[r]);
                acc[r] = ffma2(tp[r][1], wm23, acc[r]);
            }
        }
#pragma unroll
        for (int j = 0; j < 2; j++) {
            if ((mC >> (12 + q + 4 * j)) & 1) {    // alpha chunk j
                ull wa01, wa23;
                lds2(wa01, wa23, swb + 8192 + j * 2048);
#pragma unroll
                for (int r = 0; r < 4; r++) {
                    acc[4 + r] = ffma2(tp[r][2*j],   wa01, acc[4 + r]);
                    acc[4 + r] = ffma2(tp[r][2*j+1], wa23, acc[4 + r]);
                }
            }
        }
        float v[8];
#pragma unroll
        for (int c = 0; c < 8; c++) { float u, w; un2(acc[c], u, w); v[c] = u + w; }

        // role-rotation reduction: 9 SHFL for 8 values; lane ends with class l&7
        float f;
        {
            bool b0 = l & 1;
            float s0_ = b0 ? v[0] : v[1], k0 = b0 ? v[1] : v[0];
            k0 += __shfl_xor_sync(0xffffffffu, s0_, 1);
            float s1_ = b0 ? v[2] : v[3], k1 = b0 ? v[3] : v[2];
            k1 += __shfl_xor_sync(0xffffffffu, s1_, 1);
            float s2_ = b0 ? v[4] : v[5], k2 = b0 ? v[5] : v[4];
            k2 += __shfl_xor_sync(0xffffffffu, s2_, 1);
            float s3_ = b0 ? v[6] : v[7], k3 = b0 ? v[7] : v[6];
            k3 += __shfl_xor_sync(0xffffffffu, s3_, 1);
            bool b1_ = l & 2;
            float sm = b1_ ? k0 : k1, km = b1_ ? k1 : k0;
            km += __shfl_xor_sync(0xffffffffu, sm, 2);
            float sa = b1_ ? k2 : k3, ka = b1_ ? k3 : k2;
            ka += __shfl_xor_sync(0xffffffffu, sa, 2);
            bool b2_ = l & 4;
            float sf = b2_ ? km : ka, kf = b2_ ? ka : km;
            kf += __shfl_xor_sync(0xffffffffu, sf, 4);
            kf += __shfl_xor_sync(0xffffffffu, kf, 8);
            kf += __shfl_xor_sync(0xffffffffu, kf, 16);
            f = kf;
        }
        if (l < 8) sred[i & 1][l][q] = f;

        // prefetch stage i+2: per-(section, warp) chunk predication
        {
            unsigned mN2 = (i + 2 < 64) ? smask[i + 2] : 0u;
            unsigned d = sw2 + tid * 16;
            if ((mN2 >> q) & 1)        cp16(d,         srcp);            // W1 chunk q
            if ((mN2 >> (q + 4)) & 1)  cp16(d + 2048,  srcp + 512);      // W1 chunk q+4
            if ((mN2 >> (8 + q)) & 1)  cp16(d + 4096,  srcp + 1024);     // mu chunk q
            // mu chunks 4-7 (section k=3) are never nonzero: never copied
            if ((mN2 >> (12 + q)) & 1) cp16(d + 8192,  srcp + 2048);     // al chunk q
            if ((mN2 >> (16 + q)) & 1) cp16(d + 10240, srcp + 2560);     // al chunk q+4
            if (i + 2 < 64) srcp += 3072;
        }
        cp_commit();
        cp_wait1();          // stage i+1 resident
        __syncthreads();     // publish stage i+1 + sred exchange

        // combine quarters for my class, add b2, exchange mu<->alpha
        float4 cf = *(const float4*)&sred[i & 1][l & 7][0];
        float cv = (cf.x + cf.y) + (cf.z + cf.w);
        cv += b2s[(isA ? 64 : 0) + i];
        float pv = __shfl_xor_sync(0xffffffffu, cv, 4);
        float mu = isA ? pv : cv;
        float al = isA ? cv : pv;
        mu = fminf(fmaxf(mu, -CLAMPV), CLAMPV);
        al = fminf(fmaxf(al, -CLAMPV), CLAMPV);
        float zv = zs[l & 3][i];
        float x  = fmaf(zv, __expf(al), mu);
        ld += al;                                  // meaningful in alpha lanes

        if (q == 0 && l < 4) sx[l][i] = x;         // warp 0 records x

        float x0 = __shfl_sync(0xffffffffu, x, 0);
        float x1 = __shfl_sync(0xffffffffu, x, 1);
        float x2 = __shfl_sync(0xffffffffu, x, 2);
        float x3 = __shfl_sync(0xffffffffu, x, 3);

        // rank-1 update (register-held W1; mask-gated chunks)
        ull xx[4] = { mk2(x0, x0), mk2(x1, x1), mk2(x2, x2), mk2(x3, x3) };
        if (w1a0) {
#pragma unroll
            for (int r = 0; r < 4; r++) {
                sp[r][0] = ffma2(w01[0], xx[r], sp[r][0]);
                sp[r][1] = ffma2(w23[0], xx[r], sp[r][1]);
            }
        }
        if (w1a1) {
#pragma unroll
            for (int r = 0; r < 4; r++) {
                sp[r][2] = ffma2(w01[1], xx[r], sp[r][2]);
                sp[r][3] = ffma2(w23[1], xx[r], sp[r][3]);
            }
        }

        // lazy tanh refresh: mask-gated chunks (over-refresh safe)
#pragma unroll
        for (int j = 0; j < 2; j++) {
            if ((mC >> (20 + q + 4 * j)) & 1) {
#pragma unroll
                for (int r = 0; r < 4; r++) {
                    float a0, a1_, c0, c1;
                    un2(sp[r][2*j], a0, a1_);
                    tp[r][2*j]   = mk2(tanh_mufu(a0), tanh_mufu(a1_));
                    un2(sp[r][2*j+1], c0, c1);
                    tp[r][2*j+1] = mk2(tanh_mufu(c0), tanh_mufu(c1));
                }
            }
        }

        // rotate stage pointers
        unsigned t = sw0; sw0 = sw1; sw1 = sw2; sw2 = t;
    }

    // epilogue: warp 0 writes outputs from sx / ld classes
    if (q == 0) {
        __syncwarp();
        int base = blockIdx.x * 4;
#pragma unroll
        for (int r = 0; r < 4; r++) {
            float a = sx[r][2 * l], b = sx[r][2 * l + 1];
            if (!isfinite(a)) a = 0.f;
            if (!isfinite(b)) b = 0.f;
            *(float2*)(out_x + (base + r) * 64 + 2 * l) = make_float2(a, b);
        }
        if (l >= 4 && l < 8) {
            float L = ld;
            if (!isfinite(L)) L = 0.f;
            out_ld[base + (l - 4)] = L;
        }
    }
}

extern "C" void kernel_launch(void* const* d_in, const int* in_sizes, int n_in,
                              void* d_out, int out_size) {
    const float* z  = (const float*)d_in[0];   // (16384, 64)
    const float* W1 = (const float*)d_in[1];   // (1024, 64)
    const float* b1 = (const float*)d_in[2];   // (1024,)
    const float* W2 = (const float*)d_in[3];   // (128, 1024)
    const float* b2 = (const float*)d_in[4];   // (128,)
    float* out    = (float*)d_out;
    float* out_x  = out;                       // x: 16384*64 floats
    float* out_ld = out + B_ROWS * D_DIM;      // log_det: 16384 floats

    static int carveout_set = 0;
    if (!carveout_set) {
        cudaFuncSetAttribute(maf_main, cudaFuncAttributePreferredSharedMemoryCarveout, 100);
        carveout_set = 1;
    }

    maf_prep<<<768, 256>>>(W1, b1, W2);
    maf_main<<<B_ROWS / 4, NTHREADS>>>(z, b2, out_x, out_ld);  // 4 rows/block
}